// round 5
// baseline (speedup 1.0000x reference)
#include <cuda_runtime.h>
#include <cstdint>
#include <math.h>

#define VOCAB  32000
#define EMBED  300
#define HIDDEN 512
#define G4     2048   // 4*HIDDEN
#define BATCH  256
#define SEQ    512
#define NOUT   7

// ---------------------------------------------------------------------------
// Device scratch
// ---------------------------------------------------------------------------
__device__ float g_gx[(size_t)SEQ * BATCH * G4];   // 1 GiB  [s][b][g]
__device__ float g_h[2][BATCH * HIDDEN];
__device__ float g_c[BATCH * HIDDEN];

// ---------------------------------------------------------------------------
// Packed f32x2 helpers
// ---------------------------------------------------------------------------
__device__ __forceinline__ unsigned long long ffma2(unsigned long long a,
                                                    unsigned long long b,
                                                    unsigned long long c) {
    unsigned long long d;
    asm("fma.rn.f32x2 %0, %1, %2, %3;" : "=l"(d) : "l"(a), "l"(b), "l"(c));
    return d;
}
__device__ __forceinline__ unsigned long long dup_f32(float x) {
    unsigned long long d;
    asm("mov.b64 %0, {%1, %1};" : "=l"(d) : "f"(x));
    return d;
}
__device__ __forceinline__ float lo_f32(unsigned long long v) {
    return __uint_as_float((unsigned)(v & 0xffffffffull));
}
__device__ __forceinline__ float hi_f32(unsigned long long v) {
    return __uint_as_float((unsigned)(v >> 32));
}
__device__ __forceinline__ float sigf(float x) {
    return 1.f / (1.f + expf(-x));
}

// ---------------------------------------------------------------------------
// Kernel A: fused embedding gather + input projection GEMM.
// Conflict-fixed SMEM (padded pitches) + duplicated A operand (no dup MOVs).
//   inner loop per kk: 4 LDS.128 (a-dup) + 2 LDS.128 (b) + 32 FFMA2
// ---------------------------------------------------------------------------
#define BM 128
#define BN 128
#define BK 16
#define APITCH 130   // u64 pitch, row = 1040 B (16B aligned), STS 2-way max
#define BPITCH 132   // f32 pitch, row = 528 B (16B aligned), STS 2-way max

__global__ __launch_bounds__(256, 2) void k_embed_inproj(
    const int* __restrict__ tokens, const float* __restrict__ emb,
    const float* __restrict__ W_ih, const float* __restrict__ b_ih)
{
    __shared__ __align__(16) unsigned long long As2[BK][APITCH]; // 16,640 B
    __shared__ __align__(16) float Bs[BK][BPITCH];               //  8,448 B
    __shared__ int tok_s[BM];

    const int n0  = blockIdx.x * BN;
    const int m0  = blockIdx.y * BM;
    const int tid = threadIdx.x;

    if (tid < BM) {
        int r = m0 + tid;
        int s = r >> 8;
        int b = r & 255;
        tok_s[tid] = tokens[b * SEQ + s];
    }
    __syncthreads();

    const int tx = tid & 15;   // n
    const int ty = tid >> 4;   // m

    unsigned long long acc[8][4];
    #pragma unroll
    for (int i = 0; i < 8; i++)
        #pragma unroll
        for (int j = 0; j < 4; j++) acc[i][j] = 0ull;

    for (int k0 = 0; k0 < EMBED; k0 += BK) {
        #pragma unroll
        for (int x = 0; x < 8; x++) {
            int idx = tid + x * 256;
            int m   = idx >> 4;
            int kk  = idx & 15;
            int e   = k0 + kk;
            int t   = tok_s[m];
            float v = 0.f;
            if (t != 0 && e < EMBED) v = emb[(size_t)t * EMBED + e];
            As2[kk][m] = dup_f32(v);
        }
        #pragma unroll
        for (int x = 0; x < 8; x++) {
            int idx = tid + x * 256;
            int n   = idx >> 4;
            int kk  = idx & 15;
            int e   = k0 + kk;
            float v = 0.f;
            if (e < EMBED) v = W_ih[(size_t)(n0 + n) * EMBED + e];
            Bs[kk][n] = v;
        }
        __syncthreads();

        #pragma unroll
        for (int kk = 0; kk < BK; kk++) {
            const unsigned long long* ap = &As2[kk][ty * 8];
            ulonglong2 a01 = *(const ulonglong2*)(ap);
            ulonglong2 a23 = *(const ulonglong2*)(ap + 2);
            ulonglong2 a45 = *(const ulonglong2*)(ap + 4);
            ulonglong2 a67 = *(const ulonglong2*)(ap + 6);
            unsigned long long ad[8] = { a01.x, a01.y, a23.x, a23.y,
                                         a45.x, a45.y, a67.x, a67.y };
            const ulonglong2* bp = (const ulonglong2*)&Bs[kk][tx * 8];
            ulonglong2 b01 = bp[0], b23 = bp[1];
            unsigned long long bv[4] = { b01.x, b01.y, b23.x, b23.y };
            #pragma unroll
            for (int i = 0; i < 8; i++)
                #pragma unroll
                for (int j = 0; j < 4; j++)
                    acc[i][j] = ffma2(ad[i], bv[j], acc[i][j]);
        }
        __syncthreads();
    }

    float bias[8];
    #pragma unroll
    for (int j = 0; j < 8; j++) bias[j] = b_ih[n0 + tx * 8 + j];

    #pragma unroll
    for (int i = 0; i < 8; i++) {
        int r = m0 + ty * 8 + i;
        size_t base = (size_t)r * G4 + n0 + tx * 8;
        #pragma unroll
        for (int j = 0; j < 4; j++) {
            float2 v = make_float2(lo_f32(acc[i][j]) + bias[2 * j],
                                   hi_f32(acc[i][j]) + bias[2 * j + 1]);
            __stcg((float2*)&g_gx[base + 2 * j], v);
        }
    }
}

// ---------------------------------------------------------------------------
// Kernel B: one LSTM timestep, f32x2, 512 threads, k-split-4.
//
// CTA tile: 64 batches x 16 j (x4 gates).  Grid (32, 4) = 128 CTAs.
// ks = tid>>7 handles a k-quarter.  t7 = tid&127: jp = t7&7 (j-pair),
// bq = t7>>3 (4 batches).  Per kk: 4 LDS.64 (W j-pairs) + 2 LDS.128
// (duplicated h) + 16 FFMA2.  KC=128 chunks, true double buffering in
// dynamic SMEM (1 sync per chunk), k-split reduction in SMEM at the end.
// Epilogue operands loaded post-GEMM (low register pressure).
// ---------------------------------------------------------------------------
#define KC   128
#define NCH  (HIDDEN / KC)   // 4
#define WP   66              // W float pitch (264 B rows)
#define HP   66              // H u64 pitch (528 B rows, 16B aligned)
// dyn smem: W float[2][KC][WP] then H u64[2][KC][HP]
#define SMEM_STEP ((2 * KC * WP) * 4 + (2 * KC * HP) * 8)   // 202,752 B

__global__ __launch_bounds__(512, 1) void k_step(
    int s, const float* __restrict__ W_hh, const float* __restrict__ b_hh)
{
    extern __shared__ __align__(16) float sm[];
    float* Wb0 = sm;
    float* Wb1 = sm + KC * WP;
    unsigned long long* Hb0 = (unsigned long long*)(sm + 2 * KC * WP);
    unsigned long long* Hb1 = Hb0 + KC * HP;

    const float* __restrict__ h_in  = g_h[s & 1];
    float* __restrict__       h_out = g_h[(s & 1) ^ 1];

    const int j0  = blockIdx.x * 16;
    const int b0  = blockIdx.y * 64;
    const int tid = threadIdx.x;
    const int ks  = tid >> 7;          // k-quarter
    const int t7  = tid & 127;
    const int jp  = t7 & 7;
    const int bq  = t7 >> 3;

    const int sg_kk = tid & 127;       // staging: k fast (coalesced LDG)
    const int sg_g0 = tid >> 7;        // gl = sg_g0 + 4x

    unsigned long long acc[4][4];
    #pragma unroll
    for (int bb = 0; bb < 4; bb++)
        #pragma unroll
        for (int g = 0; g < 4; g++) acc[bb][g] = 0ull;

    float wreg[16], hreg[16];

    // prologue: chunk 0 into registers
    #pragma unroll
    for (int x = 0; x < 16; x++) {
        int gl   = sg_g0 + x * 4;
        int gate = gl >> 4, jl = gl & 15;
        wreg[x] = W_hh[(size_t)(gate * HIDDEN + j0 + jl) * HIDDEN + sg_kk];
        hreg[x] = h_in[(size_t)(b0 + gl) * HIDDEN + sg_kk];
    }

    for (int c = 0; c < NCH; c++) {
        float* Wc = (c & 1) ? Wb1 : Wb0;
        unsigned long long* Hc = (c & 1) ? Hb1 : Hb0;

        #pragma unroll
        for (int x = 0; x < 16; x++) {
            int gl = sg_g0 + x * 4;
            Wc[sg_kk * WP + gl] = wreg[x];
            Hc[sg_kk * HP + gl] = dup_f32(hreg[x]);
        }
        __syncthreads();

        if (c + 1 < NCH) {
            int kb = (c + 1) * KC + sg_kk;
            #pragma unroll
            for (int x = 0; x < 16; x++) {
                int gl   = sg_g0 + x * 4;
                int gate = gl >> 4, jl = gl & 15;
                wreg[x] = W_hh[(size_t)(gate * HIDDEN + j0 + jl) * HIDDEN + kb];
                hreg[x] = h_in[(size_t)(b0 + gl) * HIDDEN + kb];
            }
        }

        #pragma unroll 8
        for (int kk2 = 0; kk2 < KC / 4; kk2++) {
            int kl = ks * (KC / 4) + kk2;
            const unsigned long long* wr =
                (const unsigned long long*)(Wc + kl * WP);
            unsigned long long w0 = wr[jp];
            unsigned long long w1 = wr[8 + jp];
            unsigned long long w2 = wr[16 + jp];
            unsigned long long w3 = wr[24 + jp];
            const unsigned long long* hr = Hc + (size_t)kl * HP + bq * 4;
            ulonglong2 h01 = *(const ulonglong2*)hr;
            ulonglong2 h23 = *(const ulonglong2*)(hr + 2);
            unsigned long long hd[4] = { h01.x, h01.y, h23.x, h23.y };
            #pragma unroll
            for (int bb = 0; bb < 4; bb++) {
                acc[bb][0] = ffma2(hd[bb], w0, acc[bb][0]);
                acc[bb][1] = ffma2(hd[bb], w1, acc[bb][1]);
                acc[bb][2] = ffma2(hd[bb], w2, acc[bb][2]);
                acc[bb][3] = ffma2(hd[bb], w3, acc[bb][3]);
            }
        }
        __syncthreads();
    }

    // ---- k-split-4 reduction in SMEM ----
    unsigned long long* redA = (unsigned long long*)Wb0;  // 33,792 B >= 16 KB
    unsigned long long* redB = Hb0;                       // plenty

    if (ks == 1) {
        #pragma unroll
        for (int bb = 0; bb < 4; bb++)
            #pragma unroll
            for (int g = 0; g < 4; g++)
                redA[(bb * 4 + g) * 128 + t7] = acc[bb][g];
    } else if (ks == 3) {
        #pragma unroll
        for (int bb = 0; bb < 4; bb++)
            #pragma unroll
            for (int g = 0; g < 4; g++)
                redB[(bb * 4 + g) * 128 + t7] = acc[bb][g];
    }
    __syncthreads();
    if (ks == 0) {
        #pragma unroll
        for (int bb = 0; bb < 4; bb++)
            #pragma unroll
            for (int g = 0; g < 4; g++) {
                unsigned long long r = redA[(bb * 4 + g) * 128 + t7];
                acc[bb][g] = ffma2(r, dup_f32(1.f), acc[bb][g]);
            }
    } else if (ks == 2) {
        #pragma unroll
        for (int bb = 0; bb < 4; bb++)
            #pragma unroll
            for (int g = 0; g < 4; g++) {
                unsigned long long r = redB[(bb * 4 + g) * 128 + t7];
                acc[bb][g] = ffma2(r, dup_f32(1.f), acc[bb][g]);
            }
    }
    __syncthreads();
    if (ks == 2) {
        #pragma unroll
        for (int bb = 0; bb < 4; bb++)
            #pragma unroll
            for (int g = 0; g < 4; g++)
                redA[(bb * 4 + g) * 128 + t7] = acc[bb][g];
    }
    __syncthreads();

    // ---- epilogue (ks == 0 threads only) ----
    if (ks == 0) {
        float2 bh[4];
        #pragma unroll
        for (int g = 0; g < 4; g++)
            bh[g] = *(const float2*)&b_hh[g * HIDDEN + j0 + jp * 2];

        #pragma unroll
        for (int bb = 0; bb < 4; bb++) {
            int b = b0 + bq * 4 + bb;
            const float* gxp =
                g_gx + ((size_t)s * BATCH + b) * G4 + j0 + jp * 2;
            float2 cvv = *(const float2*)&g_c[b * HIDDEN + j0 + jp * 2];
            float ga[4][2];
            #pragma unroll
            for (int g = 0; g < 4; g++) {
                unsigned long long r = redA[(bb * 4 + g) * 128 + t7];
                float2 gv = *(const float2*)(gxp + g * HIDDEN);
                ga[g][0] = lo_f32(acc[bb][g]) + lo_f32(r) + gv.x + bh[g].x;
                ga[g][1] = hi_f32(acc[bb][g]) + hi_f32(r) + gv.y + bh[g].y;
            }
            float2 hv, cvo;
            #pragma unroll
            for (int jj = 0; jj < 2; jj++) {
                float ig = sigf(ga[0][jj]);
                float fg = sigf(ga[1][jj]);
                float gv = tanhf(ga[2][jj]);
                float og = sigf(ga[3][jj]);
                float cn = fg * ((jj == 0) ? cvv.x : cvv.y) + ig * gv;
                float hn = og * tanhf(cn);
                if (jj == 0) { hv.x = hn; cvo.x = cn; }
                else         { hv.y = hn; cvo.y = cn; }
            }
            *(float2*)&g_c[b * HIDDEN + j0 + jp * 2] = cvo;
            __stcg((float2*)&h_out[(size_t)b * HIDDEN + j0 + jp * 2], hv);
        }
    }
}

// ---------------------------------------------------------------------------
// Init
// ---------------------------------------------------------------------------
__global__ void k_init() {
    int i = blockIdx.x * blockDim.x + threadIdx.x;
    if (i < BATCH * HIDDEN) {
        g_h[0][i] = 0.f;
        g_c[i]    = 0.f;
    }
}

// ---------------------------------------------------------------------------
// Kernel C: logits = h_T @ W_fc^T + b_fc
// ---------------------------------------------------------------------------
__global__ __launch_bounds__(128) void k_fc(
    const float* __restrict__ W_fc, const float* __restrict__ b_fc,
    float* __restrict__ out)
{
    const int b   = blockIdx.x;
    const int tid = threadIdx.x;
    const float* __restrict__ h = g_h[0];

    float p[NOUT];
    #pragma unroll
    for (int o = 0; o < NOUT; o++) p[o] = 0.f;

    for (int jj = tid; jj < HIDDEN; jj += 128) {
        float hv = h[b * HIDDEN + jj];
        #pragma unroll
        for (int o = 0; o < NOUT; o++) p[o] += hv * W_fc[o * HIDDEN + jj];
    }

    __shared__ float redm[NOUT][128];
    #pragma unroll
    for (int o = 0; o < NOUT; o++) redm[o][tid] = p[o];
    __syncthreads();
    for (int st = 64; st > 0; st >>= 1) {
        if (tid < st) {
            #pragma unroll
            for (int o = 0; o < NOUT; o++) redm[o][tid] += redm[o][tid + st];
        }
        __syncthreads();
    }
    if (tid < NOUT) out[b * NOUT + tid] = redm[tid][0] + b_fc[tid];
}

// ---------------------------------------------------------------------------
// Launch
// ---------------------------------------------------------------------------
extern "C" void kernel_launch(void* const* d_in, const int* in_sizes, int n_in,
                              void* d_out, int out_size)
{
    const int*   tokens = (const int*)  d_in[0];
    const float* emb    = (const float*)d_in[1];
    const float* W_ih   = (const float*)d_in[2];
    const float* b_ih   = (const float*)d_in[3];
    const float* W_hh   = (const float*)d_in[4];
    const float* b_hh   = (const float*)d_in[5];
    const float* W_fc   = (const float*)d_in[6];
    const float* b_fc   = (const float*)d_in[7];
    float* out = (float*)d_out;

    static bool attr_set = false;
    if (!attr_set) {
        cudaFuncSetAttribute(k_step,
                             cudaFuncAttributeMaxDynamicSharedMemorySize,
                             SMEM_STEP);
        attr_set = true;
    }

    k_init<<<(BATCH * HIDDEN + 255) / 256, 256>>>();

    dim3 gA(G4 / BN, (BATCH * SEQ) / BM);   // (16, 1024)
    k_embed_inproj<<<gA, 256>>>(tokens, emb, W_ih, b_ih);

    dim3 gB(HIDDEN / 16, BATCH / 64);       // (32, 4) = 128 CTAs
    for (int s = 0; s < SEQ; s++)
        k_step<<<gB, 512, SMEM_STEP>>>(s, W_hh, b_hh);

    k_fc<<<BATCH, 128>>>(W_fc, b_fc, out);
}

// round 6
// speedup vs baseline: 1.4530x; 1.4530x over previous
#include <cuda_runtime.h>
#include <cuda_bf16.h>
#include <cstdint>
#include <math.h>

#define VOCAB  32000
#define EMBED  300
#define HIDDEN 512
#define G4     2048   // 4*HIDDEN
#define BATCH  256
#define SEQ    512
#define NOUT   7

// ---------------------------------------------------------------------------
// Device scratch
// ---------------------------------------------------------------------------
__device__ float g_gx[(size_t)SEQ * BATCH * G4];   // 1 GiB  [s][b][gate*512+j]
__device__ float g_c[BATCH * HIDDEN];
__device__ __nv_bfloat16 g_hh[2][BATCH * HIDDEN];  // h hi (ping-pong)
__device__ __nv_bfloat16 g_hl[2][BATCH * HIDDEN];  // h lo
// W_hh pre-split, k-major, gate-interleaved: Wp[k][n'] with n' = j*4 + gate
__device__ __nv_bfloat16 g_Wp_hi[(size_t)HIDDEN * G4];
__device__ __nv_bfloat16 g_Wp_lo[(size_t)HIDDEN * G4];

// ---------------------------------------------------------------------------
// Helpers
// ---------------------------------------------------------------------------
__device__ __forceinline__ unsigned long long ffma2(unsigned long long a,
                                                    unsigned long long b,
                                                    unsigned long long c) {
    unsigned long long d;
    asm("fma.rn.f32x2 %0, %1, %2, %3;" : "=l"(d) : "l"(a), "l"(b), "l"(c));
    return d;
}
__device__ __forceinline__ unsigned long long dup_f32(float x) {
    unsigned long long d;
    asm("mov.b64 %0, {%1, %1};" : "=l"(d) : "f"(x));
    return d;
}
__device__ __forceinline__ float lo_f32(unsigned long long v) {
    return __uint_as_float((unsigned)(v & 0xffffffffull));
}
__device__ __forceinline__ float hi_f32(unsigned long long v) {
    return __uint_as_float((unsigned)(v >> 32));
}
__device__ __forceinline__ float sigf(float x) {
    return 1.f / (1.f + expf(-x));
}
__device__ __forceinline__ uint32_t smem_u32(const void* p) {
    return (uint32_t)__cvta_generic_to_shared(p);
}
__device__ __forceinline__ void ldsm_x4(uint32_t* r, uint32_t a) {
    asm volatile("ldmatrix.sync.aligned.m8n8.x4.shared.b16 {%0,%1,%2,%3}, [%4];"
        : "=r"(r[0]), "=r"(r[1]), "=r"(r[2]), "=r"(r[3]) : "r"(a));
}
__device__ __forceinline__ void ldsm_x4_t(uint32_t* r, uint32_t a) {
    asm volatile("ldmatrix.sync.aligned.m8n8.x4.trans.shared.b16 {%0,%1,%2,%3}, [%4];"
        : "=r"(r[0]), "=r"(r[1]), "=r"(r[2]), "=r"(r[3]) : "r"(a));
}
__device__ __forceinline__ void mma_bf16(float* d, const uint32_t* a,
                                         uint32_t b0, uint32_t b1) {
    asm volatile(
        "mma.sync.aligned.m16n8k16.row.col.f32.bf16.bf16.f32 "
        "{%0,%1,%2,%3}, {%4,%5,%6,%7}, {%8,%9}, {%0,%1,%2,%3};"
        : "+f"(d[0]), "+f"(d[1]), "+f"(d[2]), "+f"(d[3])
        : "r"(a[0]), "r"(a[1]), "r"(a[2]), "r"(a[3]), "r"(b0), "r"(b1));
}
#define CP16(dst, src) \
    asm volatile("cp.async.cg.shared.global [%0], [%1], 16;" \
                 :: "r"(dst), "l"(src))
#define CP_COMMIT() asm volatile("cp.async.commit_group;")
#define CP_WAIT1()  asm volatile("cp.async.wait_group 1;")

// ---------------------------------------------------------------------------
// Kernel A: fused embedding gather + input projection GEMM (R4, proven)
// ---------------------------------------------------------------------------
#define BM 128
#define BN 128
#define BK 16
#define APITCH 130
#define BPITCH 132

__global__ __launch_bounds__(256, 2) void k_embed_inproj(
    const int* __restrict__ tokens, const float* __restrict__ emb,
    const float* __restrict__ W_ih, const float* __restrict__ b_ih)
{
    __shared__ __align__(16) unsigned long long As2[BK][APITCH];
    __shared__ __align__(16) float Bs[BK][BPITCH];
    __shared__ int tok_s[BM];

    const int n0  = blockIdx.x * BN;
    const int m0  = blockIdx.y * BM;
    const int tid = threadIdx.x;

    if (tid < BM) {
        int r = m0 + tid;
        int s = r >> 8;
        int b = r & 255;
        tok_s[tid] = tokens[b * SEQ + s];
    }
    __syncthreads();

    const int tx = tid & 15;
    const int ty = tid >> 4;

    unsigned long long acc[8][4];
    #pragma unroll
    for (int i = 0; i < 8; i++)
        #pragma unroll
        for (int j = 0; j < 4; j++) acc[i][j] = 0ull;

    for (int k0 = 0; k0 < EMBED; k0 += BK) {
        #pragma unroll
        for (int x = 0; x < 8; x++) {
            int idx = tid + x * 256;
            int m   = idx >> 4;
            int kk  = idx & 15;
            int e   = k0 + kk;
            int t   = tok_s[m];
            float v = 0.f;
            if (t != 0 && e < EMBED) v = emb[(size_t)t * EMBED + e];
            As2[kk][m] = dup_f32(v);
        }
        #pragma unroll
        for (int x = 0; x < 8; x++) {
            int idx = tid + x * 256;
            int n   = idx >> 4;
            int kk  = idx & 15;
            int e   = k0 + kk;
            float v = 0.f;
            if (e < EMBED) v = W_ih[(size_t)(n0 + n) * EMBED + e];
            Bs[kk][n] = v;
        }
        __syncthreads();

        #pragma unroll
        for (int kk = 0; kk < BK; kk++) {
            const unsigned long long* ap = &As2[kk][ty * 8];
            ulonglong2 a01 = *(const ulonglong2*)(ap);
            ulonglong2 a23 = *(const ulonglong2*)(ap + 2);
            ulonglong2 a45 = *(const ulonglong2*)(ap + 4);
            ulonglong2 a67 = *(const ulonglong2*)(ap + 6);
            unsigned long long ad[8] = { a01.x, a01.y, a23.x, a23.y,
                                         a45.x, a45.y, a67.x, a67.y };
            const ulonglong2* bp = (const ulonglong2*)&Bs[kk][tx * 8];
            ulonglong2 b01 = bp[0], b23 = bp[1];
            unsigned long long bv[4] = { b01.x, b01.y, b23.x, b23.y };
            #pragma unroll
            for (int i = 0; i < 8; i++)
                #pragma unroll
                for (int j = 0; j < 4; j++)
                    acc[i][j] = ffma2(ad[i], bv[j], acc[i][j]);
        }
        __syncthreads();
    }

    float bias[8];
    #pragma unroll
    for (int j = 0; j < 8; j++) bias[j] = b_ih[n0 + tx * 8 + j];

    #pragma unroll
    for (int i = 0; i < 8; i++) {
        int r = m0 + ty * 8 + i;
        size_t base = (size_t)r * G4 + n0 + tx * 8;
        #pragma unroll
        for (int j = 0; j < 4; j++) {
            float2 v = make_float2(lo_f32(acc[i][j]) + bias[2 * j],
                                   hi_f32(acc[i][j]) + bias[2 * j + 1]);
            __stcg((float2*)&g_gx[base + 2 * j], v);
        }
    }
}

// ---------------------------------------------------------------------------
// Prep: split W_hh into bf16 hi/lo, k-major, gate-interleaved (n' = j*4+gate)
// ---------------------------------------------------------------------------
__global__ void k_prep_w(const float* __restrict__ W_hh) {
    int idx = blockIdx.x * 256 + threadIdx.x;    // = k*2048 + n'
    int k  = idx >> 11;
    int np = idx & 2047;
    int gate = np & 3, j = np >> 2;
    float w = W_hh[(size_t)(gate * HIDDEN + j) * HIDDEN + k];
    __nv_bfloat16 hi = __float2bfloat16(w);
    g_Wp_hi[idx] = hi;
    g_Wp_lo[idx] = __float2bfloat16(w - __bfloat162float(hi));
}

// ---------------------------------------------------------------------------
// Kernel B: one LSTM step on tensor cores (split-bf16, 3 MMAs = ~fp32).
// CTA 64b x 64n', grid (32, 4) = 128 CTAs, 256 threads (8 warps: 4b x 2n).
// cp.async double-buffered K-chunks of 64. Epilogue: C -> SMEM -> fused
// cell update; h written back as bf16 hi/lo for the next step.
// ---------------------------------------------------------------------------
#define TKC   64
#define PITCH 72                       // bf16 elems per smem row (144 B)
#define TSZ   (TKC * PITCH)            // elems per tile buffer (4608)
#define SMEM_MMA (8 * TSZ * 2)         // 73,728 B

__global__ __launch_bounds__(256, 1) void k_step_mma(
    int s, const float* __restrict__ b_hh)
{
    extern __shared__ __align__(16) __nv_bfloat16 smem[];
    __nv_bfloat16* As_hi = smem;                 // [2][64][PITCH]
    __nv_bfloat16* As_lo = smem + 2 * TSZ;
    __nv_bfloat16* Bs_hi = smem + 4 * TSZ;
    __nv_bfloat16* Bs_lo = smem + 6 * TSZ;
    float* Csm = (float*)smem;                   // epilogue alias, pitch 68

    const int tid = threadIdx.x;
    const int n0  = blockIdx.x * 64;
    const int b0  = blockIdx.y * 64;
    const int src = s & 1, dst = src ^ 1;

    const __nv_bfloat16* __restrict__ hhi = g_hh[src];
    const __nv_bfloat16* __restrict__ hlo = g_hl[src];

    // staging map: 64 rows x 64 elems; thread -> row = tid>>2, 2x16B chunks
    const int ld_row = tid >> 2;
    const int ld_c0  = (tid & 3) * 16;

    auto issue = [&](int c) {
        int buf = c & 1;
        int k0  = c * TKC;
        // A hi/lo: rows = b, cols = k
        {
            uint32_t d = smem_u32(As_hi + buf * TSZ + ld_row * PITCH + ld_c0);
            const __nv_bfloat16* sp =
                hhi + (size_t)(b0 + ld_row) * HIDDEN + k0 + ld_c0;
            CP16(d, sp); CP16(d + 16, sp + 8);
        }
        {
            uint32_t d = smem_u32(As_lo + buf * TSZ + ld_row * PITCH + ld_c0);
            const __nv_bfloat16* sp =
                hlo + (size_t)(b0 + ld_row) * HIDDEN + k0 + ld_c0;
            CP16(d, sp); CP16(d + 16, sp + 8);
        }
        // B hi/lo: rows = k, cols = n'
        {
            uint32_t d = smem_u32(Bs_hi + buf * TSZ + ld_row * PITCH + ld_c0);
            const __nv_bfloat16* sp =
                g_Wp_hi + (size_t)(k0 + ld_row) * G4 + n0 + ld_c0;
            CP16(d, sp); CP16(d + 16, sp + 8);
        }
        {
            uint32_t d = smem_u32(Bs_lo + buf * TSZ + ld_row * PITCH + ld_c0);
            const __nv_bfloat16* sp =
                g_Wp_lo + (size_t)(k0 + ld_row) * G4 + n0 + ld_c0;
            CP16(d, sp); CP16(d + 16, sp + 8);
        }
    };

    issue(0); CP_COMMIT();
    issue(1); CP_COMMIT();

    const int wid  = tid >> 5;
    const int lane = tid & 31;
    const int wb   = (wid & 3) * 16;     // warp b offset in tile
    const int wn   = (wid >> 2) * 32;    // warp n' offset in tile

    // ldmatrix lane address components
    const int a_row = wb + (lane & 15);
    const int a_co  = (lane >> 4) * 8;
    const int b_ro  = (lane & 15);
    const int b_co  = wn + ((lane >> 4) & 1) * 8;

    float acc[4][4];
    #pragma unroll
    for (int nt = 0; nt < 4; nt++)
        #pragma unroll
        for (int i = 0; i < 4; i++) acc[nt][i] = 0.f;

    for (int c = 0; c < HIDDEN / TKC; c++) {
        CP_WAIT1();
        __syncthreads();
        int buf = c & 1;
        const __nv_bfloat16* Ah = As_hi + buf * TSZ;
        const __nv_bfloat16* Al = As_lo + buf * TSZ;
        const __nv_bfloat16* Bh = Bs_hi + buf * TSZ;
        const __nv_bfloat16* Bl = Bs_lo + buf * TSZ;

        #pragma unroll
        for (int ks = 0; ks < TKC / 16; ks++) {
            uint32_t ahi[4], alo[4];
            ldsm_x4(ahi, smem_u32(Ah + a_row * PITCH + ks * 16 + a_co));
            ldsm_x4(alo, smem_u32(Al + a_row * PITCH + ks * 16 + a_co));
            uint32_t bhi[8], blo[8];
            ldsm_x4_t(bhi,     smem_u32(Bh + (ks * 16 + b_ro) * PITCH + b_co));
            ldsm_x4_t(bhi + 4, smem_u32(Bh + (ks * 16 + b_ro) * PITCH + b_co + 16));
            ldsm_x4_t(blo,     smem_u32(Bl + (ks * 16 + b_ro) * PITCH + b_co));
            ldsm_x4_t(blo + 4, smem_u32(Bl + (ks * 16 + b_ro) * PITCH + b_co + 16));
            #pragma unroll
            for (int nt = 0; nt < 4; nt++) {
                mma_bf16(acc[nt], ahi, bhi[nt * 2], bhi[nt * 2 + 1]);
                mma_bf16(acc[nt], ahi, blo[nt * 2], blo[nt * 2 + 1]);
                mma_bf16(acc[nt], alo, bhi[nt * 2], bhi[nt * 2 + 1]);
            }
        }
        __syncthreads();
        if (c + 2 < HIDDEN / TKC) issue(c + 2);
        CP_COMMIT();
    }

    // ---- stage C to SMEM (alias over operand buffers; all reads done) ----
    #pragma unroll
    for (int nt = 0; nt < 4; nt++) {
        int r0  = wb + (lane >> 2);
        int col = wn + nt * 8 + (lane & 3) * 2;
        *(float2*)&Csm[r0 * 68 + col]       = make_float2(acc[nt][0], acc[nt][1]);
        *(float2*)&Csm[(r0 + 8) * 68 + col] = make_float2(acc[nt][2], acc[nt][3]);
    }
    __syncthreads();

    // ---- fused cell update: 1024 (b, j) pairs, 4 per thread ----
    const int jt0 = n0 >> 2;   // j tile base (16 j per CTA)
    #pragma unroll
    for (int t = 0; t < 4; t++) {
        int idx = tid + t * 256;
        int jl = idx & 15, bl = idx >> 4;
        int b = b0 + bl, j = jt0 + jl;
        float4 gq = *(const float4*)&Csm[bl * 68 + jl * 4];  // i,f,g,o
        const float* gxp = g_gx + ((size_t)s * BATCH + b) * G4 + j;
        float gi = gq.x + gxp[0]           + b_hh[j];
        float gf = gq.y + gxp[HIDDEN]      + b_hh[HIDDEN + j];
        float gg = gq.z + gxp[2 * HIDDEN]  + b_hh[2 * HIDDEN + j];
        float go = gq.w + gxp[3 * HIDDEN]  + b_hh[3 * HIDDEN + j];
        float ig = sigf(gi), fg = sigf(gf);
        float gv = tanhf(gg), og = sigf(go);
        int ci = b * HIDDEN + j;
        float cn = fg * g_c[ci] + ig * gv;
        g_c[ci] = cn;
        float hn = og * tanhf(cn);
        __nv_bfloat16 hi = __float2bfloat16(hn);
        g_hh[dst][ci] = hi;
        g_hl[dst][ci] = __float2bfloat16(hn - __bfloat162float(hi));
    }
}

// ---------------------------------------------------------------------------
// Init: zero h0 (hi/lo) and c0
// ---------------------------------------------------------------------------
__global__ void k_init() {
    int i = blockIdx.x * blockDim.x + threadIdx.x;
    if (i < BATCH * HIDDEN) {
        g_c[i]       = 0.f;
        g_hh[0][i]   = __float2bfloat16(0.f);
        g_hl[0][i]   = __float2bfloat16(0.f);
    }
}

// ---------------------------------------------------------------------------
// Kernel C: logits = h_T @ W_fc^T + b_fc   (h_T = hi+lo in buffers [0])
// ---------------------------------------------------------------------------
__global__ __launch_bounds__(128) void k_fc(
    const float* __restrict__ W_fc, const float* __restrict__ b_fc,
    float* __restrict__ out)
{
    const int b   = blockIdx.x;
    const int tid = threadIdx.x;

    float p[NOUT];
    #pragma unroll
    for (int o = 0; o < NOUT; o++) p[o] = 0.f;

    for (int jj = tid; jj < HIDDEN; jj += 128) {
        float hv = __bfloat162float(g_hh[0][b * HIDDEN + jj]) +
                   __bfloat162float(g_hl[0][b * HIDDEN + jj]);
        #pragma unroll
        for (int o = 0; o < NOUT; o++) p[o] += hv * W_fc[o * HIDDEN + jj];
    }

    __shared__ float redm[NOUT][128];
    #pragma unroll
    for (int o = 0; o < NOUT; o++) redm[o][tid] = p[o];
    __syncthreads();
    for (int st = 64; st > 0; st >>= 1) {
        if (tid < st) {
            #pragma unroll
            for (int o = 0; o < NOUT; o++) redm[o][tid] += redm[o][tid + st];
        }
        __syncthreads();
    }
    if (tid < NOUT) out[b * NOUT + tid] = redm[tid][0] + b_fc[tid];
}

// ---------------------------------------------------------------------------
// Launch
// ---------------------------------------------------------------------------
extern "C" void kernel_launch(void* const* d_in, const int* in_sizes, int n_in,
                              void* d_out, int out_size)
{
    const int*   tokens = (const int*)  d_in[0];
    const float* emb    = (const float*)d_in[1];
    const float* W_ih   = (const float*)d_in[2];
    const float* b_ih   = (const float*)d_in[3];
    const float* W_hh   = (const float*)d_in[4];
    const float* b_hh   = (const float*)d_in[5];
    const float* W_fc   = (const float*)d_in[6];
    const float* b_fc   = (const float*)d_in[7];
    float* out = (float*)d_out;

    static bool attr_set = false;
    if (!attr_set) {
        cudaFuncSetAttribute(k_step_mma,
                             cudaFuncAttributeMaxDynamicSharedMemorySize,
                             SMEM_MMA);
        attr_set = true;
    }

    k_init<<<(BATCH * HIDDEN + 255) / 256, 256>>>();
    k_prep_w<<<(HIDDEN * G4) / 256, 256>>>(W_hh);

    dim3 gA(G4 / BN, (BATCH * SEQ) / BM);   // (16, 1024)
    k_embed_inproj<<<gA, 256>>>(tokens, emb, W_ih, b_ih);

    dim3 gS(G4 / 64, BATCH / 64);           // (32, 4) = 128 CTAs
    for (int s = 0; s < SEQ; s++)
        k_step_mma<<<gS, 256, SMEM_MMA>>>(s, b_hh);

    k_fc<<<BATCH, 128>>>(W_fc, b_fc, out);
}

// round 8
// speedup vs baseline: 1.6270x; 1.1197x over previous
#include <cuda_runtime.h>
#include <cuda_bf16.h>
#include <cstdint>
#include <math.h>

#define VOCAB  32000
#define EMBED  300
#define HIDDEN 512
#define G4     2048   // 4*HIDDEN
#define BATCH  256
#define SEQ    512
#define NOUT   7

// ---------------------------------------------------------------------------
// Device scratch
// ---------------------------------------------------------------------------
__device__ float g_gx[(size_t)SEQ * BATCH * G4];   // 1 GiB  [s][b][gate*512+j]
__device__ float g_c[BATCH * HIDDEN];
__device__ __nv_bfloat16 g_hh[2][BATCH * HIDDEN];  // h hi (ping-pong)
__device__ __nv_bfloat16 g_hl[2][BATCH * HIDDEN];  // h lo
// W_hh pre-split, k-major, gate-interleaved: Wp[k][n'] with n' = j*4 + gate
__device__ __nv_bfloat16 g_Wp_hi[(size_t)HIDDEN * G4];
__device__ __nv_bfloat16 g_Wp_lo[(size_t)HIDDEN * G4];

// ---------------------------------------------------------------------------
// Helpers
// ---------------------------------------------------------------------------
__device__ __forceinline__ unsigned long long ffma2(unsigned long long a,
                                                    unsigned long long b,
                                                    unsigned long long c) {
    unsigned long long d;
    asm("fma.rn.f32x2 %0, %1, %2, %3;" : "=l"(d) : "l"(a), "l"(b), "l"(c));
    return d;
}
__device__ __forceinline__ unsigned long long dup_f32(float x) {
    unsigned long long d;
    asm("mov.b64 %0, {%1, %1};" : "=l"(d) : "f"(x));
    return d;
}
__device__ __forceinline__ float lo_f32(unsigned long long v) {
    return __uint_as_float((unsigned)(v & 0xffffffffull));
}
__device__ __forceinline__ float hi_f32(unsigned long long v) {
    return __uint_as_float((unsigned)(v >> 32));
}
__device__ __forceinline__ float sigf(float x) {
    return 1.f / (1.f + expf(-x));
}
__device__ __forceinline__ uint32_t smem_u32(const void* p) {
    return (uint32_t)__cvta_generic_to_shared(p);
}
__device__ __forceinline__ void ldsm_x4(uint32_t* r, uint32_t a) {
    asm volatile("ldmatrix.sync.aligned.m8n8.x4.shared.b16 {%0,%1,%2,%3}, [%4];"
        : "=r"(r[0]), "=r"(r[1]), "=r"(r[2]), "=r"(r[3]) : "r"(a));
}
__device__ __forceinline__ void ldsm_x4_t(uint32_t* r, uint32_t a) {
    asm volatile("ldmatrix.sync.aligned.m8n8.x4.trans.shared.b16 {%0,%1,%2,%3}, [%4];"
        : "=r"(r[0]), "=r"(r[1]), "=r"(r[2]), "=r"(r[3]) : "r"(a));
}
__device__ __forceinline__ void mma_bf16(float* d, const uint32_t* a,
                                         uint32_t b0, uint32_t b1) {
    asm volatile(
        "mma.sync.aligned.m16n8k16.row.col.f32.bf16.bf16.f32 "
        "{%0,%1,%2,%3}, {%4,%5,%6,%7}, {%8,%9}, {%0,%1,%2,%3};"
        : "+f"(d[0]), "+f"(d[1]), "+f"(d[2]), "+f"(d[3])
        : "r"(a[0]), "r"(a[1]), "r"(a[2]), "r"(a[3]), "r"(b0), "r"(b1));
}
#define CP16(dst, src) \
    asm volatile("cp.async.cg.shared.global [%0], [%1], 16;" \
                 :: "r"(dst), "l"(src))
#define CP_COMMIT() asm volatile("cp.async.commit_group;")
#define CP_WAIT1()  asm volatile("cp.async.wait_group 1;")

// ---------------------------------------------------------------------------
// Kernel A: fused embedding gather + input projection GEMM (proven)
// ---------------------------------------------------------------------------
#define BM 128
#define BN 128
#define BK 16
#define APITCH 130
#define BPITCH 132

__global__ __launch_bounds__(256, 2) void k_embed_inproj(
    const int* __restrict__ tokens, const float* __restrict__ emb,
    const float* __restrict__ W_ih, const float* __restrict__ b_ih)
{
    __shared__ __align__(16) unsigned long long As2[BK][APITCH];
    __shared__ __align__(16) float Bs[BK][BPITCH];
    __shared__ int tok_s[BM];

    const int n0  = blockIdx.x * BN;
    const int m0  = blockIdx.y * BM;
    const int tid = threadIdx.x;

    if (tid < BM) {
        int r = m0 + tid;
        int s = r >> 8;
        int b = r & 255;
        tok_s[tid] = tokens[b * SEQ + s];
    }
    __syncthreads();

    const int tx = tid & 15;
    const int ty = tid >> 4;

    unsigned long long acc[8][4];
    #pragma unroll
    for (int i = 0; i < 8; i++)
        #pragma unroll
        for (int j = 0; j < 4; j++) acc[i][j] = 0ull;

    for (int k0 = 0; k0 < EMBED; k0 += BK) {
        #pragma unroll
        for (int x = 0; x < 8; x++) {
            int idx = tid + x * 256;
            int m   = idx >> 4;
            int kk  = idx & 15;
            int e   = k0 + kk;
            int t   = tok_s[m];
            float v = 0.f;
            if (t != 0 && e < EMBED) v = emb[(size_t)t * EMBED + e];
            As2[kk][m] = dup_f32(v);
        }
        #pragma unroll
        for (int x = 0; x < 8; x++) {
            int idx = tid + x * 256;
            int n   = idx >> 4;
            int kk  = idx & 15;
            int e   = k0 + kk;
            float v = 0.f;
            if (e < EMBED) v = W_ih[(size_t)(n0 + n) * EMBED + e];
            Bs[kk][n] = v;
        }
        __syncthreads();

        #pragma unroll
        for (int kk = 0; kk < BK; kk++) {
            const unsigned long long* ap = &As2[kk][ty * 8];
            ulonglong2 a01 = *(const ulonglong2*)(ap);
            ulonglong2 a23 = *(const ulonglong2*)(ap + 2);
            ulonglong2 a45 = *(const ulonglong2*)(ap + 4);
            ulonglong2 a67 = *(const ulonglong2*)(ap + 6);
            unsigned long long ad[8] = { a01.x, a01.y, a23.x, a23.y,
                                         a45.x, a45.y, a67.x, a67.y };
            const ulonglong2* bp = (const ulonglong2*)&Bs[kk][tx * 8];
            ulonglong2 b01 = bp[0], b23 = bp[1];
            unsigned long long bv[4] = { b01.x, b01.y, b23.x, b23.y };
            #pragma unroll
            for (int i = 0; i < 8; i++)
                #pragma unroll
                for (int j = 0; j < 4; j++)
                    acc[i][j] = ffma2(ad[i], bv[j], acc[i][j]);
        }
        __syncthreads();
    }

    float bias[8];
    #pragma unroll
    for (int j = 0; j < 8; j++) bias[j] = b_ih[n0 + tx * 8 + j];

    #pragma unroll
    for (int i = 0; i < 8; i++) {
        int r = m0 + ty * 8 + i;
        size_t base = (size_t)r * G4 + n0 + tx * 8;
        #pragma unroll
        for (int j = 0; j < 4; j++) {
            float2 v = make_float2(lo_f32(acc[i][j]) + bias[2 * j],
                                   hi_f32(acc[i][j]) + bias[2 * j + 1]);
            __stcg((float2*)&g_gx[base + 2 * j], v);
        }
    }
}

// ---------------------------------------------------------------------------
// Prep: split W_hh into bf16 hi/lo, k-major, gate-interleaved (n' = j*4+gate)
// ---------------------------------------------------------------------------
__global__ void k_prep_w(const float* __restrict__ W_hh) {
    int idx = blockIdx.x * 256 + threadIdx.x;    // = k*2048 + n'
    int k  = idx >> 11;
    int np = idx & 2047;
    int gate = np & 3, j = np >> 2;
    float w = W_hh[(size_t)(gate * HIDDEN + j) * HIDDEN + k];
    __nv_bfloat16 hi = __float2bfloat16(w);
    g_Wp_hi[idx] = hi;
    g_Wp_lo[idx] = __float2bfloat16(w - __bfloat162float(hi));
}

// ---------------------------------------------------------------------------
// Kernel B: one LSTM step on tensor cores (split-bf16, 3 MMAs ~ fp32).
// v2.1: 512 threads / 16 warps (warp tile 16b x 16n'), independent
// accumulator chains per split term, 3-stage cp.async ring, 1 sync per
// chunk.  CTA 64b x 64n', grid (32, 4) = 128 CTAs.
// Stage layout (elements): [Ahi | Alo | Bhi | Blo], each TSZ.
// ---------------------------------------------------------------------------
#define TKC    64
#define PITCH  72                      // bf16 elems per smem row (144 B)
#define TSZ    (TKC * PITCH)           // 4608 elems per tile
#define STAGE  (4 * TSZ)               // elems per stage
#define NSTAGE 3
#define NCHUNK (HIDDEN / TKC)          // 8
#define SMEM_MMA (NSTAGE * STAGE * 2)  // 110,592 B

__global__ __launch_bounds__(512, 1) void k_step_mma(
    int s, const float* __restrict__ b_hh)
{
    extern __shared__ __align__(16) __nv_bfloat16 smem[];
    float* Csm = (float*)smem;                   // epilogue alias (17,408 B)

    const int tid = threadIdx.x;
    const int n0  = blockIdx.x * 64;
    const int b0  = blockIdx.y * 64;
    const int src = s & 1, dst = src ^ 1;

    const __nv_bfloat16* __restrict__ hhi = g_hh[src];
    const __nv_bfloat16* __restrict__ hlo = g_hl[src];

    // staging map: row = tid>>3 (0..63), col chunk = (tid&7)*8 elems (16 B)
    const int ld_row = tid >> 3;
    const int ld_c0  = (tid & 7) * 8;

    auto issue = [&](int c) {
        __nv_bfloat16* st = smem + (c % NSTAGE) * STAGE;
        int k0 = c * TKC;
        uint32_t d0 = smem_u32(st + ld_row * PITCH + ld_c0);
        // byte offsets between sub-tiles: TSZ elems = 2*TSZ bytes
        CP16(d0,               hhi + (size_t)(b0 + ld_row) * HIDDEN + k0 + ld_c0);
        CP16(d0 + 2 * TSZ,     hlo + (size_t)(b0 + ld_row) * HIDDEN + k0 + ld_c0);
        CP16(d0 + 4 * TSZ,     g_Wp_hi + (size_t)(k0 + ld_row) * G4 + n0 + ld_c0);
        CP16(d0 + 6 * TSZ,     g_Wp_lo + (size_t)(k0 + ld_row) * G4 + n0 + ld_c0);
    };

    issue(0); CP_COMMIT();
    issue(1); CP_COMMIT();

    const int wid  = tid >> 5;
    const int lane = tid & 31;
    const int wb   = (wid & 3) * 16;     // warp b offset
    const int wn   = (wid >> 2) * 16;    // warp n' offset

    const int a_row = wb + (lane & 15);
    const int a_co  = (lane >> 4) * 8;
    const int b_ro  = (lane & 15);
    const int b_co  = wn + (lane >> 4) * 8;

    float accm[2][4], acc1[2][4], acc2[2][4];
    #pragma unroll
    for (int nt = 0; nt < 2; nt++)
        #pragma unroll
        for (int i = 0; i < 4; i++) {
            accm[nt][i] = 0.f; acc1[nt][i] = 0.f; acc2[nt][i] = 0.f;
        }

    for (int c = 0; c < NCHUNK; c++) {
        CP_WAIT1();
        __syncthreads();
        if (c + 2 < NCHUNK) issue(c + 2);
        CP_COMMIT();

        // consumer offsets in ELEMENTS: compact layout
        const __nv_bfloat16* st = smem + (c % NSTAGE) * STAGE;
        const __nv_bfloat16* Ah = st;
        const __nv_bfloat16* Al = st + TSZ;
        const __nv_bfloat16* Bh = st + 2 * TSZ;
        const __nv_bfloat16* Bl = st + 3 * TSZ;

        #pragma unroll
        for (int ks = 0; ks < TKC / 16; ks++) {
            uint32_t ahi[4], alo[4], bhi[4], blo[4];
            ldsm_x4(ahi,   smem_u32(Ah + a_row * PITCH + ks * 16 + a_co));
            ldsm_x4(alo,   smem_u32(Al + a_row * PITCH + ks * 16 + a_co));
            ldsm_x4_t(bhi, smem_u32(Bh + (ks * 16 + b_ro) * PITCH + b_co));
            ldsm_x4_t(blo, smem_u32(Bl + (ks * 16 + b_ro) * PITCH + b_co));
            #pragma unroll
            for (int nt = 0; nt < 2; nt++) {
                mma_bf16(accm[nt], ahi, bhi[nt * 2], bhi[nt * 2 + 1]);
                mma_bf16(acc1[nt], ahi, blo[nt * 2], blo[nt * 2 + 1]);
                mma_bf16(acc2[nt], alo, bhi[nt * 2], bhi[nt * 2 + 1]);
            }
        }
    }

    // fold split terms
    #pragma unroll
    for (int nt = 0; nt < 2; nt++)
        #pragma unroll
        for (int i = 0; i < 4; i++)
            accm[nt][i] += acc1[nt][i] + acc2[nt][i];

    // ---- stage C to SMEM ----
    // Last chunk (c=7) uses stage 1; Csm aliases stage 0 (last used c=6,
    // all reads of which completed before the c=7 barrier).  Each warp
    // writes only its own disjoint 16x16 tile.
    __syncthreads();
    #pragma unroll
    for (int nt = 0; nt < 2; nt++) {
        int r0  = wb + (lane >> 2);
        int col = wn + nt * 8 + (lane & 3) * 2;
        *(float2*)&Csm[r0 * 68 + col]       = make_float2(accm[nt][0], accm[nt][1]);
        *(float2*)&Csm[(r0 + 8) * 68 + col] = make_float2(accm[nt][2], accm[nt][3]);
    }
    __syncthreads();

    // ---- fused cell update: 1024 (b, j) pairs, 2 per thread ----
    const int jt0 = n0 >> 2;   // 16 j per CTA
    #pragma unroll
    for (int t = 0; t < 2; t++) {
        int idx = tid + t * 512;
        int jl = idx & 15, bl = idx >> 4;
        int b = b0 + bl, j = jt0 + jl;
        float4 gq = *(const float4*)&Csm[bl * 68 + jl * 4];  // i,f,g,o
        const float* gxp = g_gx + ((size_t)s * BATCH + b) * G4 + j;
        float gi = gq.x + gxp[0]           + b_hh[j];
        float gf = gq.y + gxp[HIDDEN]      + b_hh[HIDDEN + j];
        float gg = gq.z + gxp[2 * HIDDEN]  + b_hh[2 * HIDDEN + j];
        float go = gq.w + gxp[3 * HIDDEN]  + b_hh[3 * HIDDEN + j];
        float ig = sigf(gi), fg = sigf(gf);
        float gv = tanhf(gg), og = sigf(go);
        int ci = b * HIDDEN + j;
        float cn = fg * g_c[ci] + ig * gv;
        g_c[ci] = cn;
        float hn = og * tanhf(cn);
        __nv_bfloat16 hi = __float2bfloat16(hn);
        g_hh[dst][ci] = hi;
        g_hl[dst][ci] = __float2bfloat16(hn - __bfloat162float(hi));
    }
}

// ---------------------------------------------------------------------------
// Init
// ---------------------------------------------------------------------------
__global__ void k_init() {
    int i = blockIdx.x * blockDim.x + threadIdx.x;
    if (i < BATCH * HIDDEN) {
        g_c[i]     = 0.f;
        g_hh[0][i] = __float2bfloat16(0.f);
        g_hl[0][i] = __float2bfloat16(0.f);
    }
}

// ---------------------------------------------------------------------------
// Kernel C: logits = h_T @ W_fc^T + b_fc
// ---------------------------------------------------------------------------
__global__ __launch_bounds__(128) void k_fc(
    const float* __restrict__ W_fc, const float* __restrict__ b_fc,
    float* __restrict__ out)
{
    const int b   = blockIdx.x;
    const int tid = threadIdx.x;

    float p[NOUT];
    #pragma unroll
    for (int o = 0; o < NOUT; o++) p[o] = 0.f;

    for (int jj = tid; jj < HIDDEN; jj += 128) {
        float hv = __bfloat162float(g_hh[0][b * HIDDEN + jj]) +
                   __bfloat162float(g_hl[0][b * HIDDEN + jj]);
        #pragma unroll
        for (int o = 0; o < NOUT; o++) p[o] += hv * W_fc[o * HIDDEN + jj];
    }

    __shared__ float redm[NOUT][128];
    #pragma unroll
    for (int o = 0; o < NOUT; o++) redm[o][tid] = p[o];
    __syncthreads();
    for (int st = 64; st > 0; st >>= 1) {
        if (tid < st) {
            #pragma unroll
            for (int o = 0; o < NOUT; o++) redm[o][tid] += redm[o][tid + st];
        }
        __syncthreads();
    }
    if (tid < NOUT) out[b * NOUT + tid] = redm[tid][0] + b_fc[tid];
}

// ---------------------------------------------------------------------------
// Launch
// ---------------------------------------------------------------------------
extern "C" void kernel_launch(void* const* d_in, const int* in_sizes, int n_in,
                              void* d_out, int out_size)
{
    const int*   tokens = (const int*)  d_in[0];
    const float* emb    = (const float*)d_in[1];
    const float* W_ih   = (const float*)d_in[2];
    const float* b_ih   = (const float*)d_in[3];
    const float* W_hh   = (const float*)d_in[4];
    const float* b_hh   = (const float*)d_in[5];
    const float* W_fc   = (const float*)d_in[6];
    const float* b_fc   = (const float*)d_in[7];
    float* out = (float*)d_out;

    static bool attr_set = false;
    if (!attr_set) {
        cudaFuncSetAttribute(k_step_mma,
                             cudaFuncAttributeMaxDynamicSharedMemorySize,
                             SMEM_MMA);
        attr_set = true;
    }

    k_init<<<(BATCH * HIDDEN + 255) / 256, 256>>>();
    k_prep_w<<<(HIDDEN * G4) / 256, 256>>>(W_hh);

    dim3 gA(G4 / BN, (BATCH * SEQ) / BM);   // (16, 1024)
    k_embed_inproj<<<gA, 256>>>(tokens, emb, W_ih, b_ih);

    dim3 gS(G4 / 64, BATCH / 64);           // (32, 4) = 128 CTAs
    for (int s = 0; s < SEQ; s++)
        k_step_mma<<<gS, 512, SMEM_MMA>>>(s, b_hh);

    k_fc<<<BATCH, 128>>>(W_fc, b_fc, out);
}

// round 9
// speedup vs baseline: 1.7530x; 1.0774x over previous
#include <cuda_runtime.h>
#include <cuda_bf16.h>
#include <cstdint>
#include <math.h>

#define VOCAB  32000
#define EMBED  300
#define HIDDEN 512
#define G4     2048   // 4*HIDDEN
#define BATCH  256
#define SEQ    512
#define NOUT   7

// ---------------------------------------------------------------------------
// Device scratch
// ---------------------------------------------------------------------------
__device__ float g_gx[(size_t)SEQ * BATCH * G4];   // 1 GiB  [s][b][gate*512+j]
__device__ __nv_bfloat16 g_hh[2][BATCH * HIDDEN];  // h hi (ping-pong)
__device__ __nv_bfloat16 g_hl[2][BATCH * HIDDEN];  // h lo
// W_hh pre-split, k-major, gate-interleaved: Wp[k][n'] with n' = j*4 + gate
__device__ __nv_bfloat16 g_Wp_hi[(size_t)HIDDEN * G4];
__device__ __nv_bfloat16 g_Wp_lo[(size_t)HIDDEN * G4];
__device__ unsigned g_cnt;
__device__ unsigned g_epoch;

// ---------------------------------------------------------------------------
// Helpers
// ---------------------------------------------------------------------------
__device__ __forceinline__ unsigned long long ffma2(unsigned long long a,
                                                    unsigned long long b,
                                                    unsigned long long c) {
    unsigned long long d;
    asm("fma.rn.f32x2 %0, %1, %2, %3;" : "=l"(d) : "l"(a), "l"(b), "l"(c));
    return d;
}
__device__ __forceinline__ unsigned long long dup_f32(float x) {
    unsigned long long d;
    asm("mov.b64 %0, {%1, %1};" : "=l"(d) : "f"(x));
    return d;
}
__device__ __forceinline__ float lo_f32(unsigned long long v) {
    return __uint_as_float((unsigned)(v & 0xffffffffull));
}
__device__ __forceinline__ float hi_f32(unsigned long long v) {
    return __uint_as_float((unsigned)(v >> 32));
}
__device__ __forceinline__ float sigf(float x) {
    return 1.f / (1.f + expf(-x));
}
__device__ __forceinline__ uint32_t smem_u32(const void* p) {
    return (uint32_t)__cvta_generic_to_shared(p);
}
__device__ __forceinline__ void ldsm_x4(uint32_t* r, uint32_t a) {
    asm volatile("ldmatrix.sync.aligned.m8n8.x4.shared.b16 {%0,%1,%2,%3}, [%4];"
        : "=r"(r[0]), "=r"(r[1]), "=r"(r[2]), "=r"(r[3]) : "r"(a));
}
__device__ __forceinline__ void ldsm_x4_t(uint32_t* r, uint32_t a) {
    asm volatile("ldmatrix.sync.aligned.m8n8.x4.trans.shared.b16 {%0,%1,%2,%3}, [%4];"
        : "=r"(r[0]), "=r"(r[1]), "=r"(r[2]), "=r"(r[3]) : "r"(a));
}
__device__ __forceinline__ void mma_bf16(float* d, const uint32_t* a,
                                         uint32_t b0, uint32_t b1) {
    asm volatile(
        "mma.sync.aligned.m16n8k16.row.col.f32.bf16.bf16.f32 "
        "{%0,%1,%2,%3}, {%4,%5,%6,%7}, {%8,%9}, {%0,%1,%2,%3};"
        : "+f"(d[0]), "+f"(d[1]), "+f"(d[2]), "+f"(d[3])
        : "r"(a[0]), "r"(a[1]), "r"(a[2]), "r"(a[3]), "r"(b0), "r"(b1));
}
#define CP16(dst, src) \
    asm volatile("cp.async.cg.shared.global [%0], [%1], 16;" \
                 :: "r"(dst), "l"(src))
#define CP_COMMIT() asm volatile("cp.async.commit_group;")
#define CP_WAIT1()  asm volatile("cp.async.wait_group 1;")
#define CP_WAIT0()  asm volatile("cp.async.wait_group 0;")

// ---------------------------------------------------------------------------
// Kernel A: fused embedding gather + input projection GEMM (proven)
// ---------------------------------------------------------------------------
#define BM 128
#define BN 128
#define BK 16
#define APITCH 130
#define BPITCH 132

__global__ __launch_bounds__(256, 2) void k_embed_inproj(
    const int* __restrict__ tokens, const float* __restrict__ emb,
    const float* __restrict__ W_ih, const float* __restrict__ b_ih)
{
    __shared__ __align__(16) unsigned long long As2[BK][APITCH];
    __shared__ __align__(16) float Bs[BK][BPITCH];
    __shared__ int tok_s[BM];

    const int n0  = blockIdx.x * BN;
    const int m0  = blockIdx.y * BM;
    const int tid = threadIdx.x;

    if (tid < BM) {
        int r = m0 + tid;
        int s = r >> 8;
        int b = r & 255;
        tok_s[tid] = tokens[b * SEQ + s];
    }
    __syncthreads();

    const int tx = tid & 15;
    const int ty = tid >> 4;

    unsigned long long acc[8][4];
    #pragma unroll
    for (int i = 0; i < 8; i++)
        #pragma unroll
        for (int j = 0; j < 4; j++) acc[i][j] = 0ull;

    for (int k0 = 0; k0 < EMBED; k0 += BK) {
        #pragma unroll
        for (int x = 0; x < 8; x++) {
            int idx = tid + x * 256;
            int m   = idx >> 4;
            int kk  = idx & 15;
            int e   = k0 + kk;
            int t   = tok_s[m];
            float v = 0.f;
            if (t != 0 && e < EMBED) v = emb[(size_t)t * EMBED + e];
            As2[kk][m] = dup_f32(v);
        }
        #pragma unroll
        for (int x = 0; x < 8; x++) {
            int idx = tid + x * 256;
            int n   = idx >> 4;
            int kk  = idx & 15;
            int e   = k0 + kk;
            float v = 0.f;
            if (e < EMBED) v = W_ih[(size_t)(n0 + n) * EMBED + e];
            Bs[kk][n] = v;
        }
        __syncthreads();

        #pragma unroll
        for (int kk = 0; kk < BK; kk++) {
            const unsigned long long* ap = &As2[kk][ty * 8];
            ulonglong2 a01 = *(const ulonglong2*)(ap);
            ulonglong2 a23 = *(const ulonglong2*)(ap + 2);
            ulonglong2 a45 = *(const ulonglong2*)(ap + 4);
            ulonglong2 a67 = *(const ulonglong2*)(ap + 6);
            unsigned long long ad[8] = { a01.x, a01.y, a23.x, a23.y,
                                         a45.x, a45.y, a67.x, a67.y };
            const ulonglong2* bp = (const ulonglong2*)&Bs[kk][tx * 8];
            ulonglong2 b01 = bp[0], b23 = bp[1];
            unsigned long long bv[4] = { b01.x, b01.y, b23.x, b23.y };
            #pragma unroll
            for (int i = 0; i < 8; i++)
                #pragma unroll
                for (int j = 0; j < 4; j++)
                    acc[i][j] = ffma2(ad[i], bv[j], acc[i][j]);
        }
        __syncthreads();
    }

    float bias[8];
    #pragma unroll
    for (int j = 0; j < 8; j++) bias[j] = b_ih[n0 + tx * 8 + j];

    #pragma unroll
    for (int i = 0; i < 8; i++) {
        int r = m0 + ty * 8 + i;
        size_t base = (size_t)r * G4 + n0 + tx * 8;
        #pragma unroll
        for (int j = 0; j < 4; j++) {
            float2 v = make_float2(lo_f32(acc[i][j]) + bias[2 * j],
                                   hi_f32(acc[i][j]) + bias[2 * j + 1]);
            __stcg((float2*)&g_gx[base + 2 * j], v);
        }
    }
}

// ---------------------------------------------------------------------------
// Prep: split W_hh into bf16 hi/lo, k-major, gate-interleaved (n' = j*4+gate)
// ---------------------------------------------------------------------------
__global__ void k_prep_w(const float* __restrict__ W_hh) {
    int idx = blockIdx.x * 256 + threadIdx.x;    // = k*2048 + n'
    int k  = idx >> 11;
    int np = idx & 2047;
    int gate = np & 3, j = np >> 2;
    float w = W_hh[(size_t)(gate * HIDDEN + j) * HIDDEN + k];
    __nv_bfloat16 hi = __float2bfloat16(w);
    g_Wp_hi[idx] = hi;
    g_Wp_lo[idx] = __float2bfloat16(w - __bfloat162float(hi));
}

// ---------------------------------------------------------------------------
// Persistent LSTM kernel (split-bf16 tensor cores, W resident in SMEM).
//
// 128 CTAs x 512 threads (16 warps, warp tile 16b x 16n').  CTA tile
// 64b x 64n' fixed for all 512 steps; W slice (hi+lo) resident in SMEM.
// Per step: h streamed via 3-stage cp.async ring (8 chunks of k=64),
// gx prefetched with chunk 0, c-state in registers, grid epoch barrier.
//
// SMEM layout (bf16 elems):
//   [0, 36864)          W hi  [512 k][72 pitch]
//   [36864, 73728)      W lo
//   [73728, 101376)     h ring: 3 stages x (Ahi 4608 | Alo 4608)
//   [101376, 109568)    gxs (as float[64][64], 16 KB)
//   Csm (epilogue) aliases ring stage 0.
// ---------------------------------------------------------------------------
#define PITCH   72
#define WSPLIT  (HIDDEN * PITCH)           // 36864 elems per split
#define RING0   (2 * WSPLIT)               // 73728
#define HTILE   (64 * PITCH)               // 4608 elems (one split)
#define HSTAGE  (2 * HTILE)                // 9216 elems per ring stage
#define GXS_OFF (RING0 + 3 * HSTAGE)       // 101376 elems
#define SMEM_PERSIST ((GXS_OFF + 8192) * 2)  // 219,136 B

__global__ __launch_bounds__(512, 1) void k_lstm_persist(
    const float* __restrict__ b_hh)
{
    extern __shared__ __align__(16) __nv_bfloat16 smem[];
    float* Csm   = (float*)(smem + RING0);         // stage-0 alias
    float* gxs   = (float*)(smem + GXS_OFF);

    const int tid = threadIdx.x;
    const int cta = blockIdx.x;
    const int n0  = (cta & 31) * 64;     // 32 n'-tiles
    const int b0  = (cta >> 5) * 64;     // 4 b-tiles
    const int jt0 = n0 >> 2;

    // ---- one-time W load into SMEM (hi | lo), layout [k][PITCH] ----
    #pragma unroll
    for (int x = 0; x < 8; x++) {
        int o   = tid + x * 512;          // 0..4095
        int k   = o >> 3;
        int seg = (o & 7) * 8;
        uint32_t d = smem_u32(smem + k * PITCH + seg);
        CP16(d, g_Wp_hi + (size_t)k * G4 + n0 + seg);
        uint32_t d2 = smem_u32(smem + WSPLIT + k * PITCH + seg);
        CP16(d2, g_Wp_lo + (size_t)k * G4 + n0 + seg);
    }
    CP_COMMIT();

    // ---- epilogue-resident state: bias + c in registers ----
    float bh[2][4], creg[2];
    #pragma unroll
    for (int t = 0; t < 2; t++) {
        int idx = tid + t * 512;
        int jl  = idx & 15;
        int j   = jt0 + jl;
        creg[t] = 0.f;
        #pragma unroll
        for (int g = 0; g < 4; g++) bh[t][g] = b_hh[g * HIDDEN + j];
    }

    CP_WAIT0();
    __syncthreads();

    // staging map for h chunks: row = tid>>3 (0..63 b), col = (tid&7)*8
    const int ld_row = tid >> 3;
    const int ld_c0  = (tid & 7) * 8;

    const int wid  = tid >> 5;
    const int lane = tid & 31;
    const int wb   = (wid & 3) * 16;
    const int wn   = (wid >> 2) * 16;
    const int a_row = wb + (lane & 15);
    const int a_co  = (lane >> 4) * 8;
    const int b_ro  = (lane & 15);
    const int b_co  = wn + (lane >> 4) * 8;

    for (int s = 0; s < SEQ; s++) {
        const __nv_bfloat16* __restrict__ hhi = g_hh[s & 1];
        const __nv_bfloat16* __restrict__ hlo = g_hl[s & 1];
        __nv_bfloat16* __restrict__ ohh = g_hh[(s & 1) ^ 1];
        __nv_bfloat16* __restrict__ ohl = g_hl[(s & 1) ^ 1];

        // ---- issue gx prefetch + h chunk 0 (one group), then chunk 1 ----
        {
            const float* gbase = g_gx + ((size_t)s * BATCH + b0) * G4 + jt0;
            #pragma unroll
            for (int t = 0; t < 2; t++) {
                int o = tid * 2 + t;              // 0..1023
                int b = o >> 4, gate = (o >> 2) & 3, q = (o & 3) * 4;
                uint32_t d = smem_u32(gxs + b * 64 + gate * 16 + q);
                CP16(d, gbase + (size_t)b * G4 + gate * HIDDEN + q);
            }
        }
        #pragma unroll
        for (int c0 = 0; c0 < 2; c0++) {
            __nv_bfloat16* st = smem + RING0 + c0 * HSTAGE;
            uint32_t d = smem_u32(st + ld_row * PITCH + ld_c0);
            const size_t off = (size_t)(b0 + ld_row) * HIDDEN + c0 * 64 + ld_c0;
            CP16(d,                hhi + off);
            CP16(d + 2 * HTILE,    hlo + off);   // byte offset = HTILE elems
            CP_COMMIT();
        }

        float accm[2][4], acc1[2][4], acc2[2][4];
        #pragma unroll
        for (int nt = 0; nt < 2; nt++)
            #pragma unroll
            for (int i = 0; i < 4; i++) {
                accm[nt][i] = 0.f; acc1[nt][i] = 0.f; acc2[nt][i] = 0.f;
            }

        for (int c = 0; c < 8; c++) {
            CP_WAIT1();
            __syncthreads();
            if (c + 2 < 8) {
                int cn = c + 2;
                __nv_bfloat16* st = smem + RING0 + (cn % 3) * HSTAGE;
                uint32_t d = smem_u32(st + ld_row * PITCH + ld_c0);
                const size_t off =
                    (size_t)(b0 + ld_row) * HIDDEN + cn * 64 + ld_c0;
                CP16(d,             hhi + off);
                CP16(d + 2 * HTILE, hlo + off);
            }
            CP_COMMIT();

            const __nv_bfloat16* Ah = smem + RING0 + (c % 3) * HSTAGE;
            const __nv_bfloat16* Al = Ah + HTILE;

            #pragma unroll
            for (int ks = 0; ks < 4; ks++) {
                uint32_t ahi[4], alo[4], bhi[4], blo[4];
                ldsm_x4(ahi, smem_u32(Ah + a_row * PITCH + ks * 16 + a_co));
                ldsm_x4(alo, smem_u32(Al + a_row * PITCH + ks * 16 + a_co));
                int krow = c * 64 + ks * 16 + b_ro;
                ldsm_x4_t(bhi, smem_u32(smem + krow * PITCH + b_co));
                ldsm_x4_t(blo, smem_u32(smem + WSPLIT + krow * PITCH + b_co));
                #pragma unroll
                for (int nt = 0; nt < 2; nt++) {
                    mma_bf16(accm[nt], ahi, bhi[nt * 2], bhi[nt * 2 + 1]);
                    mma_bf16(acc1[nt], ahi, blo[nt * 2], blo[nt * 2 + 1]);
                    mma_bf16(acc2[nt], alo, bhi[nt * 2], bhi[nt * 2 + 1]);
                }
            }
        }

        #pragma unroll
        for (int nt = 0; nt < 2; nt++)
            #pragma unroll
            for (int i = 0; i < 4; i++)
                accm[nt][i] += acc1[nt][i] + acc2[nt][i];

        // ---- stage C into SMEM (stage-0 alias; stage 0 last read c=6,
        //      all warps passed the c=7 barrier) ----
        __syncthreads();
        #pragma unroll
        for (int nt = 0; nt < 2; nt++) {
            int r0  = wb + (lane >> 2);
            int col = wn + nt * 8 + (lane & 3) * 2;
            *(float2*)&Csm[r0 * 68 + col] =
                make_float2(accm[nt][0], accm[nt][1]);
            *(float2*)&Csm[(r0 + 8) * 68 + col] =
                make_float2(accm[nt][2], accm[nt][3]);
        }
        __syncthreads();

        // ---- fused cell update: 1024 (b, j) pairs, 2 per thread ----
        #pragma unroll
        for (int t = 0; t < 2; t++) {
            int idx = tid + t * 512;
            int jl = idx & 15, bl = idx >> 4;
            int b = b0 + bl, j = jt0 + jl;
            float4 gq = *(const float4*)&Csm[bl * 68 + jl * 4];  // i,f,g,o
            const float* gr = gxs + bl * 64;
            float gi = gq.x + gr[jl]      + bh[t][0];
            float gf = gq.y + gr[16 + jl] + bh[t][1];
            float gg = gq.z + gr[32 + jl] + bh[t][2];
            float go = gq.w + gr[48 + jl] + bh[t][3];
            float ig = sigf(gi), fg = sigf(gf);
            float gv = tanhf(gg), og = sigf(go);
            float cn = fg * creg[t] + ig * gv;
            creg[t] = cn;
            float hn = og * tanhf(cn);
            int ci = b * HIDDEN + j;
            __nv_bfloat16 hi = __float2bfloat16(hn);
            ohh[ci] = hi;
            ohl[ci] = __float2bfloat16(hn - __bfloat162float(hi));
        }

        // ---- grid-wide epoch barrier ----
        __syncthreads();
        if (tid == 0) {
            __threadfence();
            unsigned a = atomicAdd(&g_cnt, 1u);
            if (a == gridDim.x - 1) {
                g_cnt = 0;
                __threadfence();
                *(volatile unsigned*)&g_epoch = (unsigned)(s + 1);
            } else {
                while (*(volatile unsigned*)&g_epoch < (unsigned)(s + 1)) { }
            }
            __threadfence();
        }
        __syncthreads();
    }
}

// ---------------------------------------------------------------------------
// Init
// ---------------------------------------------------------------------------
__global__ void k_init() {
    int i = blockIdx.x * blockDim.x + threadIdx.x;
    if (i < BATCH * HIDDEN) {
        g_hh[0][i] = __float2bfloat16(0.f);
        g_hl[0][i] = __float2bfloat16(0.f);
    }
    if (i == 0) { g_cnt = 0u; g_epoch = 0u; }
}

// ---------------------------------------------------------------------------
// Kernel C: logits = h_T @ W_fc^T + b_fc  (h_T = hi+lo in buffers [0])
// ---------------------------------------------------------------------------
__global__ __launch_bounds__(128) void k_fc(
    const float* __restrict__ W_fc, const float* __restrict__ b_fc,
    float* __restrict__ out)
{
    const int b   = blockIdx.x;
    const int tid = threadIdx.x;

    float p[NOUT];
    #pragma unroll
    for (int o = 0; o < NOUT; o++) p[o] = 0.f;

    for (int jj = tid; jj < HIDDEN; jj += 128) {
        float hv = __bfloat162float(g_hh[0][b * HIDDEN + jj]) +
                   __bfloat162float(g_hl[0][b * HIDDEN + jj]);
        #pragma unroll
        for (int o = 0; o < NOUT; o++) p[o] += hv * W_fc[o * HIDDEN + jj];
    }

    __shared__ float redm[NOUT][128];
    #pragma unroll
    for (int o = 0; o < NOUT; o++) redm[o][tid] = p[o];
    __syncthreads();
    for (int st = 64; st > 0; st >>= 1) {
        if (tid < st) {
            #pragma unroll
            for (int o = 0; o < NOUT; o++) redm[o][tid] += redm[o][tid + st];
        }
        __syncthreads();
    }
    if (tid < NOUT) out[b * NOUT + tid] = redm[tid][0] + b_fc[tid];
}

// ---------------------------------------------------------------------------
// Launch
// ---------------------------------------------------------------------------
extern "C" void kernel_launch(void* const* d_in, const int* in_sizes, int n_in,
                              void* d_out, int out_size)
{
    const int*   tokens = (const int*)  d_in[0];
    const float* emb    = (const float*)d_in[1];
    const float* W_ih   = (const float*)d_in[2];
    const float* b_ih   = (const float*)d_in[3];
    const float* W_hh   = (const float*)d_in[4];
    const float* b_hh   = (const float*)d_in[5];
    const float* W_fc   = (const float*)d_in[6];
    const float* b_fc   = (const float*)d_in[7];
    float* out = (float*)d_out;

    static bool attr_set = false;
    if (!attr_set) {
        cudaFuncSetAttribute(k_lstm_persist,
                             cudaFuncAttributeMaxDynamicSharedMemorySize,
                             SMEM_PERSIST);
        attr_set = true;
    }

    k_init<<<(BATCH * HIDDEN + 255) / 256, 256>>>();
    k_prep_w<<<(HIDDEN * G4) / 256, 256>>>(W_hh);

    dim3 gA(G4 / BN, (BATCH * SEQ) / BM);   // (16, 1024)
    k_embed_inproj<<<gA, 256>>>(tokens, emb, W_ih, b_ih);

    k_lstm_persist<<<128, 512, SMEM_PERSIST>>>(b_hh);

    k_fc<<<BATCH, 128>>>(W_fc, b_fc, out);
}

// round 10
// speedup vs baseline: 2.7345x; 1.5599x over previous
#include <cuda_runtime.h>
#include <cuda_bf16.h>
#include <cstdint>
#include <math.h>

#define VOCAB  32000
#define EMBED  300
#define KA     320           // padded K for the input projection (5 x 64)
#define HIDDEN 512
#define G4     2048          // 4*HIDDEN
#define BATCH  256
#define SEQ    512
#define NOUT   7

// ---------------------------------------------------------------------------
// Device scratch
// ---------------------------------------------------------------------------
__device__ float g_gx[(size_t)SEQ * BATCH * G4];   // 1 GiB  [s][b][gate*512+j]
__device__ __nv_bfloat16 g_hh[2][BATCH * HIDDEN];  // h hi (ping-pong)
__device__ __nv_bfloat16 g_hl[2][BATCH * HIDDEN];  // h lo
// W_hh pre-split, k-major, gate-interleaved: Wp[k][n'] with n' = j*4 + gate
__device__ __nv_bfloat16 g_Wp_hi[(size_t)HIDDEN * G4];
__device__ __nv_bfloat16 g_Wp_lo[(size_t)HIDDEN * G4];
// embedding table pre-split (row 0 zeroed, cols 300..319 zero)
__device__ __nv_bfloat16 g_emb_hi[(size_t)VOCAB * KA];
__device__ __nv_bfloat16 g_emb_lo[(size_t)VOCAB * KA];
// W_ih pre-split, k-major: Wih[k][g], k padded to 320
__device__ __nv_bfloat16 g_wih_hi[(size_t)KA * G4];
__device__ __nv_bfloat16 g_wih_lo[(size_t)KA * G4];
__device__ unsigned g_cnt;
__device__ unsigned g_epoch;

// ---------------------------------------------------------------------------
// Helpers
// ---------------------------------------------------------------------------
__device__ __forceinline__ float sigf(float x) {
    return 1.f / (1.f + expf(-x));
}
__device__ __forceinline__ uint32_t smem_u32(const void* p) {
    return (uint32_t)__cvta_generic_to_shared(p);
}
__device__ __forceinline__ void ldsm_x4(uint32_t* r, uint32_t a) {
    asm volatile("ldmatrix.sync.aligned.m8n8.x4.shared.b16 {%0,%1,%2,%3}, [%4];"
        : "=r"(r[0]), "=r"(r[1]), "=r"(r[2]), "=r"(r[3]) : "r"(a));
}
__device__ __forceinline__ void ldsm_x4_t(uint32_t* r, uint32_t a) {
    asm volatile("ldmatrix.sync.aligned.m8n8.x4.trans.shared.b16 {%0,%1,%2,%3}, [%4];"
        : "=r"(r[0]), "=r"(r[1]), "=r"(r[2]), "=r"(r[3]) : "r"(a));
}
__device__ __forceinline__ void mma_bf16(float* d, const uint32_t* a,
                                         uint32_t b0, uint32_t b1) {
    asm volatile(
        "mma.sync.aligned.m16n8k16.row.col.f32.bf16.bf16.f32 "
        "{%0,%1,%2,%3}, {%4,%5,%6,%7}, {%8,%9}, {%0,%1,%2,%3};"
        : "+f"(d[0]), "+f"(d[1]), "+f"(d[2]), "+f"(d[3])
        : "r"(a[0]), "r"(a[1]), "r"(a[2]), "r"(a[3]), "r"(b0), "r"(b1));
}
#define CP16(dst, src) \
    asm volatile("cp.async.cg.shared.global [%0], [%1], 16;" \
                 :: "r"(dst), "l"(src))
#define CP_COMMIT() asm volatile("cp.async.commit_group;")
#define CP_WAIT1()  asm volatile("cp.async.wait_group 1;")
#define CP_WAIT0()  asm volatile("cp.async.wait_group 0;")

// ---------------------------------------------------------------------------
// Prep kernels: split fp32 operands into bf16 hi/lo
// ---------------------------------------------------------------------------
__global__ void k_prep_w(const float* __restrict__ W_hh) {
    int idx = blockIdx.x * 256 + threadIdx.x;    // = k*2048 + n'
    int k  = idx >> 11;
    int np = idx & 2047;
    int gate = np & 3, j = np >> 2;
    float w = W_hh[(size_t)(gate * HIDDEN + j) * HIDDEN + k];
    __nv_bfloat16 hi = __float2bfloat16(w);
    g_Wp_hi[idx] = hi;
    g_Wp_lo[idx] = __float2bfloat16(w - __bfloat162float(hi));
}

__global__ void k_prep_wih(const float* __restrict__ W_ih) {
    int idx = blockIdx.x * 256 + threadIdx.x;    // = k*2048 + g
    int k = idx >> 11;
    int g = idx & 2047;
    float w = (k < EMBED) ? W_ih[(size_t)g * EMBED + k] : 0.f;
    __nv_bfloat16 hi = __float2bfloat16(w);
    g_wih_hi[idx] = hi;
    g_wih_lo[idx] = __float2bfloat16(w - __bfloat162float(hi));
}

__global__ void k_prep_emb(const float* __restrict__ emb) {
    size_t idx = (size_t)blockIdx.x * 256 + threadIdx.x;  // row*KA + col
    int col = (int)(idx % KA);
    int row = (int)(idx / KA);
    float v = (row != 0 && col < EMBED) ? emb[(size_t)row * EMBED + col] : 0.f;
    __nv_bfloat16 hi = __float2bfloat16(v);
    g_emb_hi[idx] = hi;
    g_emb_lo[idx] = __float2bfloat16(v - __bfloat162float(hi));
}

// ---------------------------------------------------------------------------
// Kernel A (MMA): fused embedding gather + input projection, split-bf16.
//   gx[r, g] = sum_k embsplit[tok(r), k] * wihsplit[k, g] + b_ih[g]
// CTA 128m x 64n, 512 threads / 16 warps (8 m-groups x 2 n-groups),
// warp tile 16m x 32n.  K = 320 in 5 chunks of 64, 3-stage cp.async ring.
// ---------------------------------------------------------------------------
#define PITCH  72
#define AHSZ   (128 * PITCH)            // 9216 elems: A hi tile
#define BHSZ   (64 * PITCH)             // 4608 elems: B hi tile
#define BOFF   (2 * AHSZ)               // B hi elem offset within stage
#define ASTAGE (2 * AHSZ + 2 * BHSZ)    // 27648 elems per stage
#define NCHA   5                        // 320 / 64
#define SMEM_EMB (3 * ASTAGE * 2)       // 165,888 B

__global__ __launch_bounds__(512, 1) void k_embed_mma(
    const int* __restrict__ tokens, const float* __restrict__ b_ih)
{
    extern __shared__ __align__(16) __nv_bfloat16 smem[];
    __shared__ int tok_s[128];

    const int tid = threadIdx.x;
    const int n0  = blockIdx.x * 64;
    const int m0  = blockIdx.y * 128;

    if (tid < 128) {
        int r = m0 + tid;
        int s = r >> 8;
        int b = r & 255;
        tok_s[tid] = tokens[b * SEQ + s];
    }
    __syncthreads();

    // staging maps
    const int ar   = tid >> 2;           // A row 0..127
    const int aseg = (tid & 3) * 2;      // 2 segs of 8 elems each
    const int br   = tid >> 3;           // B row 0..63
    const int bseg = tid & 7;

    auto issue = [&](int c) {
        __nv_bfloat16* st = smem + (c % 3) * ASTAGE;
        int k0 = c * 64;
        const size_t abase = (size_t)tok_s[ar] * KA + k0;
        #pragma unroll
        for (int t = 0; t < 2; t++) {
            int seg = aseg + t;
            uint32_t d = smem_u32(st + ar * PITCH + seg * 8);
            CP16(d,            g_emb_hi + abase + seg * 8);
            CP16(d + 2 * AHSZ, g_emb_lo + abase + seg * 8);  // bytes
        }
        const size_t bbase = (size_t)(k0 + br) * G4 + n0 + bseg * 8;
        uint32_t d = smem_u32(st + BOFF + br * PITCH + bseg * 8);
        CP16(d,            g_wih_hi + bbase);
        CP16(d + 2 * BHSZ, g_wih_lo + bbase);
    };

    issue(0); CP_COMMIT();
    issue(1); CP_COMMIT();

    const int wid  = tid >> 5;
    const int lane = tid & 31;
    const int wm   = (wid & 7) * 16;     // 8 m-groups
    const int wn   = (wid >> 3) * 32;    // 2 n-groups

    const int a_row = wm + (lane & 15);
    const int a_co  = (lane >> 4) * 8;
    const int b_ro  = (lane & 15);

    float accm[4][4], acc1[4][4], acc2[4][4];
    #pragma unroll
    for (int nt = 0; nt < 4; nt++)
        #pragma unroll
        for (int i = 0; i < 4; i++) {
            accm[nt][i] = 0.f; acc1[nt][i] = 0.f; acc2[nt][i] = 0.f;
        }

    for (int c = 0; c < NCHA; c++) {
        CP_WAIT1();
        __syncthreads();
        if (c + 2 < NCHA) issue(c + 2);
        CP_COMMIT();

        const __nv_bfloat16* st = smem + (c % 3) * ASTAGE;
        const __nv_bfloat16* Ah = st;
        const __nv_bfloat16* Al = st + AHSZ;
        const __nv_bfloat16* Bh = st + BOFF;
        const __nv_bfloat16* Bl = st + BOFF + BHSZ;

        #pragma unroll
        for (int ks = 0; ks < 4; ks++) {
            uint32_t ahi[4], alo[4], bhi[8], blo[8];
            ldsm_x4(ahi, smem_u32(Ah + a_row * PITCH + ks * 16 + a_co));
            ldsm_x4(alo, smem_u32(Al + a_row * PITCH + ks * 16 + a_co));
            int kr = ks * 16 + b_ro;
            int bc0 = wn + (lane >> 4) * 8;
            ldsm_x4_t(bhi,     smem_u32(Bh + kr * PITCH + bc0));
            ldsm_x4_t(bhi + 4, smem_u32(Bh + kr * PITCH + bc0 + 16));
            ldsm_x4_t(blo,     smem_u32(Bl + kr * PITCH + bc0));
            ldsm_x4_t(blo + 4, smem_u32(Bl + kr * PITCH + bc0 + 16));
            #pragma unroll
            for (int nt = 0; nt < 4; nt++) {
                mma_bf16(accm[nt], ahi, bhi[nt * 2], bhi[nt * 2 + 1]);
                mma_bf16(acc1[nt], ahi, blo[nt * 2], blo[nt * 2 + 1]);
                mma_bf16(acc2[nt], alo, bhi[nt * 2], bhi[nt * 2 + 1]);
            }
        }
    }

    // fold splits, add bias, store directly to gx (coalesced float2)
    #pragma unroll
    for (int nt = 0; nt < 4; nt++) {
        int col = n0 + wn + nt * 8 + (lane & 3) * 2;
        float2 bias = *(const float2*)&b_ih[col];
        float c0 = accm[nt][0] + acc1[nt][0] + acc2[nt][0] + bias.x;
        float c1 = accm[nt][1] + acc1[nt][1] + acc2[nt][1] + bias.y;
        float c2 = accm[nt][2] + acc1[nt][2] + acc2[nt][2] + bias.x;
        float c3 = accm[nt][3] + acc1[nt][3] + acc2[nt][3] + bias.y;
        size_t r0 = (size_t)(m0 + wm + (lane >> 2));
        __stcg((float2*)&g_gx[r0 * G4 + col],       make_float2(c0, c1));
        __stcg((float2*)&g_gx[(r0 + 8) * G4 + col], make_float2(c2, c3));
    }
}

// ---------------------------------------------------------------------------
// Persistent LSTM kernel (split-bf16 tensor cores, W resident in SMEM).
// (unchanged from R8 — proven)
// ---------------------------------------------------------------------------
#define WSPLIT  (HIDDEN * PITCH)           // 36864 elems per split
#define RING0   (2 * WSPLIT)               // 73728
#define HTILE   (64 * PITCH)               // 4608 elems (one split)
#define HSTAGE  (2 * HTILE)                // 9216 elems per ring stage
#define GXS_OFF (RING0 + 3 * HSTAGE)       // 101376 elems
#define SMEM_PERSIST ((GXS_OFF + 8192) * 2)  // 219,136 B

__global__ __launch_bounds__(512, 1) void k_lstm_persist(
    const float* __restrict__ b_hh)
{
    extern __shared__ __align__(16) __nv_bfloat16 smem[];
    float* Csm   = (float*)(smem + RING0);         // stage-0 alias
    float* gxs   = (float*)(smem + GXS_OFF);

    const int tid = threadIdx.x;
    const int cta = blockIdx.x;
    const int n0  = (cta & 31) * 64;     // 32 n'-tiles
    const int b0  = (cta >> 5) * 64;     // 4 b-tiles
    const int jt0 = n0 >> 2;

    #pragma unroll
    for (int x = 0; x < 8; x++) {
        int o   = tid + x * 512;
        int k   = o >> 3;
        int seg = (o & 7) * 8;
        uint32_t d = smem_u32(smem + k * PITCH + seg);
        CP16(d, g_Wp_hi + (size_t)k * G4 + n0 + seg);
        uint32_t d2 = smem_u32(smem + WSPLIT + k * PITCH + seg);
        CP16(d2, g_Wp_lo + (size_t)k * G4 + n0 + seg);
    }
    CP_COMMIT();

    float bh[2][4], creg[2];
    #pragma unroll
    for (int t = 0; t < 2; t++) {
        int idx = tid + t * 512;
        int jl  = idx & 15;
        int j   = jt0 + jl;
        creg[t] = 0.f;
        #pragma unroll
        for (int g = 0; g < 4; g++) bh[t][g] = b_hh[g * HIDDEN + j];
    }

    CP_WAIT0();
    __syncthreads();

    const int ld_row = tid >> 3;
    const int ld_c0  = (tid & 7) * 8;

    const int wid  = tid >> 5;
    const int lane = tid & 31;
    const int wb   = (wid & 3) * 16;
    const int wn   = (wid >> 2) * 16;
    const int a_row = wb + (lane & 15);
    const int a_co  = (lane >> 4) * 8;
    const int b_ro  = (lane & 15);
    const int b_co  = wn + (lane >> 4) * 8;

    for (int s = 0; s < SEQ; s++) {
        const __nv_bfloat16* __restrict__ hhi = g_hh[s & 1];
        const __nv_bfloat16* __restrict__ hlo = g_hl[s & 1];
        __nv_bfloat16* __restrict__ ohh = g_hh[(s & 1) ^ 1];
        __nv_bfloat16* __restrict__ ohl = g_hl[(s & 1) ^ 1];

        {
            const float* gbase = g_gx + ((size_t)s * BATCH + b0) * G4 + jt0;
            #pragma unroll
            for (int t = 0; t < 2; t++) {
                int o = tid * 2 + t;
                int b = o >> 4, gate = (o >> 2) & 3, q = (o & 3) * 4;
                uint32_t d = smem_u32(gxs + b * 64 + gate * 16 + q);
                CP16(d, gbase + (size_t)b * G4 + gate * HIDDEN + q);
            }
        }
        #pragma unroll
        for (int c0 = 0; c0 < 2; c0++) {
            __nv_bfloat16* st = smem + RING0 + c0 * HSTAGE;
            uint32_t d = smem_u32(st + ld_row * PITCH + ld_c0);
            const size_t off = (size_t)(b0 + ld_row) * HIDDEN + c0 * 64 + ld_c0;
            CP16(d,                hhi + off);
            CP16(d + 2 * HTILE,    hlo + off);
            CP_COMMIT();
        }

        float accm[2][4], acc1[2][4], acc2[2][4];
        #pragma unroll
        for (int nt = 0; nt < 2; nt++)
            #pragma unroll
            for (int i = 0; i < 4; i++) {
                accm[nt][i] = 0.f; acc1[nt][i] = 0.f; acc2[nt][i] = 0.f;
            }

        for (int c = 0; c < 8; c++) {
            CP_WAIT1();
            __syncthreads();
            if (c + 2 < 8) {
                int cn = c + 2;
                __nv_bfloat16* st = smem + RING0 + (cn % 3) * HSTAGE;
                uint32_t d = smem_u32(st + ld_row * PITCH + ld_c0);
                const size_t off =
                    (size_t)(b0 + ld_row) * HIDDEN + cn * 64 + ld_c0;
                CP16(d,             hhi + off);
                CP16(d + 2 * HTILE, hlo + off);
            }
            CP_COMMIT();

            const __nv_bfloat16* Ah = smem + RING0 + (c % 3) * HSTAGE;
            const __nv_bfloat16* Al = Ah + HTILE;

            #pragma unroll
            for (int ks = 0; ks < 4; ks++) {
                uint32_t ahi[4], alo[4], bhi[4], blo[4];
                ldsm_x4(ahi, smem_u32(Ah + a_row * PITCH + ks * 16 + a_co));
                ldsm_x4(alo, smem_u32(Al + a_row * PITCH + ks * 16 + a_co));
                int krow = c * 64 + ks * 16 + b_ro;
                ldsm_x4_t(bhi, smem_u32(smem + krow * PITCH + b_co));
                ldsm_x4_t(blo, smem_u32(smem + WSPLIT + krow * PITCH + b_co));
                #pragma unroll
                for (int nt = 0; nt < 2; nt++) {
                    mma_bf16(accm[nt], ahi, bhi[nt * 2], bhi[nt * 2 + 1]);
                    mma_bf16(acc1[nt], ahi, blo[nt * 2], blo[nt * 2 + 1]);
                    mma_bf16(acc2[nt], alo, bhi[nt * 2], bhi[nt * 2 + 1]);
                }
            }
        }

        #pragma unroll
        for (int nt = 0; nt < 2; nt++)
            #pragma unroll
            for (int i = 0; i < 4; i++)
                accm[nt][i] += acc1[nt][i] + acc2[nt][i];

        __syncthreads();
        #pragma unroll
        for (int nt = 0; nt < 2; nt++) {
            int r0  = wb + (lane >> 2);
            int col = wn + nt * 8 + (lane & 3) * 2;
            *(float2*)&Csm[r0 * 68 + col] =
                make_float2(accm[nt][0], accm[nt][1]);
            *(float2*)&Csm[(r0 + 8) * 68 + col] =
                make_float2(accm[nt][2], accm[nt][3]);
        }
        __syncthreads();

        #pragma unroll
        for (int t = 0; t < 2; t++) {
            int idx = tid + t * 512;
            int jl = idx & 15, bl = idx >> 4;
            int b = b0 + bl, j = jt0 + jl;
            float4 gq = *(const float4*)&Csm[bl * 68 + jl * 4];  // i,f,g,o
            const float* gr = gxs + bl * 64;
            float gi = gq.x + gr[jl]      + bh[t][0];
            float gf = gq.y + gr[16 + jl] + bh[t][1];
            float gg = gq.z + gr[32 + jl] + bh[t][2];
            float go = gq.w + gr[48 + jl] + bh[t][3];
            float ig = sigf(gi), fg = sigf(gf);
            float gv = tanhf(gg), og = sigf(go);
            float cn = fg * creg[t] + ig * gv;
            creg[t] = cn;
            float hn = og * tanhf(cn);
            int ci = b * HIDDEN + j;
            __nv_bfloat16 hi = __float2bfloat16(hn);
            ohh[ci] = hi;
            ohl[ci] = __float2bfloat16(hn - __bfloat162float(hi));
        }

        __syncthreads();
        if (tid == 0) {
            __threadfence();
            unsigned a = atomicAdd(&g_cnt, 1u);
            if (a == gridDim.x - 1) {
                g_cnt = 0;
                __threadfence();
                *(volatile unsigned*)&g_epoch = (unsigned)(s + 1);
            } else {
                while (*(volatile unsigned*)&g_epoch < (unsigned)(s + 1)) { }
            }
            __threadfence();
        }
        __syncthreads();
    }
}

// ---------------------------------------------------------------------------
// Init
// ---------------------------------------------------------------------------
__global__ void k_init() {
    int i = blockIdx.x * blockDim.x + threadIdx.x;
    if (i < BATCH * HIDDEN) {
        g_hh[0][i] = __float2bfloat16(0.f);
        g_hl[0][i] = __float2bfloat16(0.f);
    }
    if (i == 0) { g_cnt = 0u; g_epoch = 0u; }
}

// ---------------------------------------------------------------------------
// Kernel C: logits = h_T @ W_fc^T + b_fc  (h_T = hi+lo in buffers [0])
// ---------------------------------------------------------------------------
__global__ __launch_bounds__(128) void k_fc(
    const float* __restrict__ W_fc, const float* __restrict__ b_fc,
    float* __restrict__ out)
{
    const int b   = blockIdx.x;
    const int tid = threadIdx.x;

    float p[NOUT];
    #pragma unroll
    for (int o = 0; o < NOUT; o++) p[o] = 0.f;

    for (int jj = tid; jj < HIDDEN; jj += 128) {
        float hv = __bfloat162float(g_hh[0][b * HIDDEN + jj]) +
                   __bfloat162float(g_hl[0][b * HIDDEN + jj]);
        #pragma unroll
        for (int o = 0; o < NOUT; o++) p[o] += hv * W_fc[o * HIDDEN + jj];
    }

    __shared__ float redm[NOUT][128];
    #pragma unroll
    for (int o = 0; o < NOUT; o++) redm[o][tid] = p[o];
    __syncthreads();
    for (int st = 64; st > 0; st >>= 1) {
        if (tid < st) {
            #pragma unroll
            for (int o = 0; o < NOUT; o++) redm[o][tid] += redm[o][tid + st];
        }
        __syncthreads();
    }
    if (tid < NOUT) out[b * NOUT + tid] = redm[tid][0] + b_fc[tid];
}

// ---------------------------------------------------------------------------
// Launch
// ---------------------------------------------------------------------------
extern "C" void kernel_launch(void* const* d_in, const int* in_sizes, int n_in,
                              void* d_out, int out_size)
{
    const int*   tokens = (const int*)  d_in[0];
    const float* emb    = (const float*)d_in[1];
    const float* W_ih   = (const float*)d_in[2];
    const float* b_ih   = (const float*)d_in[3];
    const float* W_hh   = (const float*)d_in[4];
    const float* b_hh   = (const float*)d_in[5];
    const float* W_fc   = (const float*)d_in[6];
    const float* b_fc   = (const float*)d_in[7];
    float* out = (float*)d_out;

    static bool attr_set = false;
    if (!attr_set) {
        cudaFuncSetAttribute(k_lstm_persist,
                             cudaFuncAttributeMaxDynamicSharedMemorySize,
                             SMEM_PERSIST);
        cudaFuncSetAttribute(k_embed_mma,
                             cudaFuncAttributeMaxDynamicSharedMemorySize,
                             SMEM_EMB);
        attr_set = true;
    }

    k_init<<<(BATCH * HIDDEN + 255) / 256, 256>>>();
    k_prep_w<<<(HIDDEN * G4) / 256, 256>>>(W_hh);
    k_prep_wih<<<(KA * G4) / 256, 256>>>(W_ih);
    k_prep_emb<<<((size_t)VOCAB * KA) / 256, 256>>>(emb);

    dim3 gE(G4 / 64, (BATCH * SEQ) / 128);   // (32, 1024)
    k_embed_mma<<<gE, 512, SMEM_EMB>>>(tokens, b_ih);

    k_lstm_persist<<<128, 512, SMEM_PERSIST>>>(b_hh);

    k_fc<<<BATCH, 128>>>(W_fc, b_fc, out);
}

// round 12
// speedup vs baseline: 2.7871x; 1.0192x over previous
#include <cuda_runtime.h>
#include <cuda_bf16.h>
#include <cstdint>
#include <math.h>

#define VOCAB  32000
#define EMBED  300
#define KA     320
#define HIDDEN 512
#define G4     2048
#define BATCH  256
#define SEQ    512
#define NOUT   7

// ---------------------------------------------------------------------------
// Device scratch
// ---------------------------------------------------------------------------
__device__ float g_gx[(size_t)SEQ * BATCH * G4];   // [s][b][gate*512+j]
__device__ __nv_bfloat16 g_hh[2][BATCH * HIDDEN];
__device__ __nv_bfloat16 g_hl[2][BATCH * HIDDEN];
__device__ __nv_bfloat16 g_Wp_hi[(size_t)HIDDEN * G4];   // [k][n'=j*4+gate]
__device__ __nv_bfloat16 g_Wp_lo[(size_t)HIDDEN * G4];
__device__ __nv_bfloat16 g_emb_hi[(size_t)VOCAB * KA];
__device__ __nv_bfloat16 g_emb_lo[(size_t)VOCAB * KA];
__device__ __nv_bfloat16 g_wih_hi[(size_t)KA * G4];
__device__ __nv_bfloat16 g_wih_lo[(size_t)KA * G4];
// 4 independent sub-group barriers (one per b-tile), 128B padded
__device__ unsigned g_cnt4[4 * 32];
__device__ unsigned g_epoch4[4 * 32];

// ---------------------------------------------------------------------------
// Helpers
// ---------------------------------------------------------------------------
__device__ __forceinline__ float sigf(float x) {
    return 1.f / (1.f + expf(-x));
}
__device__ __forceinline__ uint32_t smem_u32(const void* p) {
    return (uint32_t)__cvta_generic_to_shared(p);
}
__device__ __forceinline__ void ldsm_x4(uint32_t* r, uint32_t a) {
    asm volatile("ldmatrix.sync.aligned.m8n8.x4.shared.b16 {%0,%1,%2,%3}, [%4];"
        : "=r"(r[0]), "=r"(r[1]), "=r"(r[2]), "=r"(r[3]) : "r"(a));
}
__device__ __forceinline__ void ldsm_x4_t(uint32_t* r, uint32_t a) {
    asm volatile("ldmatrix.sync.aligned.m8n8.x4.trans.shared.b16 {%0,%1,%2,%3}, [%4];"
        : "=r"(r[0]), "=r"(r[1]), "=r"(r[2]), "=r"(r[3]) : "r"(a));
}
__device__ __forceinline__ void mma_bf16(float* d, const uint32_t* a,
                                         uint32_t b0, uint32_t b1) {
    asm volatile(
        "mma.sync.aligned.m16n8k16.row.col.f32.bf16.bf16.f32 "
        "{%0,%1,%2,%3}, {%4,%5,%6,%7}, {%8,%9}, {%0,%1,%2,%3};"
        : "+f"(d[0]), "+f"(d[1]), "+f"(d[2]), "+f"(d[3])
        : "r"(a[0]), "r"(a[1]), "r"(a[2]), "r"(a[3]), "r"(b0), "r"(b1));
}
#define CP16(dst, src) \
    asm volatile("cp.async.cg.shared.global [%0], [%1], 16;" \
                 :: "r"(dst), "l"(src))
#define CP_COMMIT() asm volatile("cp.async.commit_group;")
#define CP_WAIT1()  asm volatile("cp.async.wait_group 1;")
#define CP_WAIT0()  asm volatile("cp.async.wait_group 0;")
#define FENCE_ACQREL_GPU() asm volatile("fence.acq_rel.gpu;" ::: "memory")

// ---------------------------------------------------------------------------
// Prep kernels
// ---------------------------------------------------------------------------
__global__ void k_prep_w(const float* __restrict__ W_hh) {
    int idx = blockIdx.x * 256 + threadIdx.x;    // = k*2048 + n'
    int k  = idx >> 11;
    int np = idx & 2047;
    int gate = np & 3, j = np >> 2;
    float w = W_hh[(size_t)(gate * HIDDEN + j) * HIDDEN + k];
    __nv_bfloat16 hi = __float2bfloat16(w);
    g_Wp_hi[idx] = hi;
    g_Wp_lo[idx] = __float2bfloat16(w - __bfloat162float(hi));
}

__global__ void k_prep_wih(const float* __restrict__ W_ih) {
    int idx = blockIdx.x * 256 + threadIdx.x;    // k*2048 + g
    int k = idx >> 11;
    int g = idx & 2047;
    float w = (k < EMBED) ? W_ih[(size_t)g * EMBED + k] : 0.f;
    __nv_bfloat16 hi = __float2bfloat16(w);
    g_wih_hi[idx] = hi;
    g_wih_lo[idx] = __float2bfloat16(w - __bfloat162float(hi));
}

__global__ void k_prep_emb(const float* __restrict__ emb) {
    size_t idx = (size_t)blockIdx.x * 256 + threadIdx.x;  // row*KA + col
    int col = (int)(idx % KA);
    int row = (int)(idx / KA);
    float v = (row != 0 && col < EMBED) ? emb[(size_t)row * EMBED + col] : 0.f;
    __nv_bfloat16 hi = __float2bfloat16(v);
    g_emb_hi[idx] = hi;
    g_emb_lo[idx] = __float2bfloat16(v - __bfloat162float(hi));
}

// ---------------------------------------------------------------------------
// Kernel A (MMA): fused embedding gather + input projection, split-bf16.
// (proven R9)
// ---------------------------------------------------------------------------
#define PITCH  72
#define AHSZ   (128 * PITCH)
#define BHSZ   (64 * PITCH)
#define BOFF   (2 * AHSZ)
#define ASTAGE (2 * AHSZ + 2 * BHSZ)
#define NCHA   5
#define SMEM_EMB (3 * ASTAGE * 2)

__global__ __launch_bounds__(512, 1) void k_embed_mma(
    const int* __restrict__ tokens, const float* __restrict__ b_ih)
{
    extern __shared__ __align__(16) __nv_bfloat16 smem[];
    __shared__ int tok_s[128];

    const int tid = threadIdx.x;
    const int n0  = blockIdx.x * 64;
    const int m0  = blockIdx.y * 128;

    if (tid < 128) {
        int r = m0 + tid;
        int s = r >> 8;
        int b = r & 255;
        tok_s[tid] = tokens[b * SEQ + s];
    }
    __syncthreads();

    const int ar   = tid >> 2;
    const int aseg = (tid & 3) * 2;
    const int br   = tid >> 3;
    const int bseg = tid & 7;

    auto issue = [&](int c) {
        __nv_bfloat16* st = smem + (c % 3) * ASTAGE;
        int k0 = c * 64;
        const size_t abase = (size_t)tok_s[ar] * KA + k0;
        #pragma unroll
        for (int t = 0; t < 2; t++) {
            int seg = aseg + t;
            uint32_t d = smem_u32(st + ar * PITCH + seg * 8);
            CP16(d,            g_emb_hi + abase + seg * 8);
            CP16(d + 2 * AHSZ, g_emb_lo + abase + seg * 8);
        }
        const size_t bbase = (size_t)(k0 + br) * G4 + n0 + bseg * 8;
        uint32_t d = smem_u32(st + BOFF + br * PITCH + bseg * 8);
        CP16(d,            g_wih_hi + bbase);
        CP16(d + 2 * BHSZ, g_wih_lo + bbase);
    };

    issue(0); CP_COMMIT();
    issue(1); CP_COMMIT();

    const int wid  = tid >> 5;
    const int lane = tid & 31;
    const int wm   = (wid & 7) * 16;
    const int wn   = (wid >> 3) * 32;

    const int a_row = wm + (lane & 15);
    const int a_co  = (lane >> 4) * 8;
    const int b_ro  = (lane & 15);

    float accm[4][4], acc1[4][4], acc2[4][4];
    #pragma unroll
    for (int nt = 0; nt < 4; nt++)
        #pragma unroll
        for (int i = 0; i < 4; i++) {
            accm[nt][i] = 0.f; acc1[nt][i] = 0.f; acc2[nt][i] = 0.f;
        }

    for (int c = 0; c < NCHA; c++) {
        CP_WAIT1();
        __syncthreads();
        if (c + 2 < NCHA) issue(c + 2);
        CP_COMMIT();

        const __nv_bfloat16* st = smem + (c % 3) * ASTAGE;
        const __nv_bfloat16* Ah = st;
        const __nv_bfloat16* Al = st + AHSZ;
        const __nv_bfloat16* Bh = st + BOFF;
        const __nv_bfloat16* Bl = st + BOFF + BHSZ;

        #pragma unroll
        for (int ks = 0; ks < 4; ks++) {
            uint32_t ahi[4], alo[4], bhi[8], blo[8];
            ldsm_x4(ahi, smem_u32(Ah + a_row * PITCH + ks * 16 + a_co));
            ldsm_x4(alo, smem_u32(Al + a_row * PITCH + ks * 16 + a_co));
            int kr = ks * 16 + b_ro;
            int bc0 = wn + (lane >> 4) * 8;
            ldsm_x4_t(bhi,     smem_u32(Bh + kr * PITCH + bc0));
            ldsm_x4_t(bhi + 4, smem_u32(Bh + kr * PITCH + bc0 + 16));
            ldsm_x4_t(blo,     smem_u32(Bl + kr * PITCH + bc0));
            ldsm_x4_t(blo + 4, smem_u32(Bl + kr * PITCH + bc0 + 16));
            #pragma unroll
            for (int nt = 0; nt < 4; nt++) {
                mma_bf16(accm[nt], ahi, bhi[nt * 2], bhi[nt * 2 + 1]);
                mma_bf16(acc1[nt], ahi, blo[nt * 2], blo[nt * 2 + 1]);
                mma_bf16(acc2[nt], alo, bhi[nt * 2], bhi[nt * 2 + 1]);
            }
        }
    }

    #pragma unroll
    for (int nt = 0; nt < 4; nt++) {
        int col = n0 + wn + nt * 8 + (lane & 3) * 2;
        float2 bias = *(const float2*)&b_ih[col];
        float c0 = accm[nt][0] + acc1[nt][0] + acc2[nt][0] + bias.x;
        float c1 = accm[nt][1] + acc1[nt][1] + acc2[nt][1] + bias.y;
        float c2 = accm[nt][2] + acc1[nt][2] + acc2[nt][2] + bias.x;
        float c3 = accm[nt][3] + acc1[nt][3] + acc2[nt][3] + bias.y;
        size_t r0 = (size_t)(m0 + wm + (lane >> 2));
        __stcg((float2*)&g_gx[r0 * G4 + col],       make_float2(c0, c1));
        __stcg((float2*)&g_gx[(r0 + 8) * G4 + col], make_float2(c2, c3));
    }
}

// ---------------------------------------------------------------------------
// Persistent LSTM kernel (split-bf16 mma.sync, W resident in SMEM).
// v3: 4 independent 32-CTA sub-group barriers (b-groups never interact),
// acq_rel fences instead of sc threadfence, one fewer syncthreads.
// ---------------------------------------------------------------------------
#define WSPLIT  (HIDDEN * PITCH)
#define RING0   (2 * WSPLIT)
#define HTILE   (64 * PITCH)
#define HSTAGE  (2 * HTILE)
#define GXS_OFF (RING0 + 3 * HSTAGE)
#define SMEM_PERSIST ((GXS_OFF + 8192) * 2)

__global__ __launch_bounds__(512, 1) void k_lstm_persist(
    const float* __restrict__ b_hh)
{
    extern __shared__ __align__(16) __nv_bfloat16 smem[];
    float* Csm   = (float*)(smem + RING0);
    float* gxs   = (float*)(smem + GXS_OFF);

    const int tid = threadIdx.x;
    const int cta = blockIdx.x;
    const int n0  = (cta & 31) * 64;
    const int bt  = cta >> 5;            // b-group 0..3
    const int b0  = bt * 64;
    const int jt0 = n0 >> 2;

    unsigned* cntp   = &g_cnt4[bt * 32];
    unsigned* epochp = &g_epoch4[bt * 32];

    #pragma unroll
    for (int x = 0; x < 8; x++) {
        int o   = tid + x * 512;
        int k   = o >> 3;
        int seg = (o & 7) * 8;
        uint32_t d = smem_u32(smem + k * PITCH + seg);
        CP16(d, g_Wp_hi + (size_t)k * G4 + n0 + seg);
        uint32_t d2 = smem_u32(smem + WSPLIT + k * PITCH + seg);
        CP16(d2, g_Wp_lo + (size_t)k * G4 + n0 + seg);
    }
    CP_COMMIT();

    float bh[2][4], creg[2];
    #pragma unroll
    for (int t = 0; t < 2; t++) {
        int idx = tid + t * 512;
        int jl  = idx & 15;
        int j   = jt0 + jl;
        creg[t] = 0.f;
        #pragma unroll
        for (int g = 0; g < 4; g++) bh[t][g] = b_hh[g * HIDDEN + j];
    }

    CP_WAIT0();
    __syncthreads();

    const int ld_row = tid >> 3;
    const int ld_c0  = (tid & 7) * 8;

    const int wid  = tid >> 5;
    const int lane = tid & 31;
    const int wb   = (wid & 3) * 16;
    const int wn   = (wid >> 2) * 16;
    const int a_row = wb + (lane & 15);
    const int a_co  = (lane >> 4) * 8;
    const int b_ro  = (lane & 15);
    const int b_co  = wn + (lane >> 4) * 8;

    for (int s = 0; s < SEQ; s++) {
        const __nv_bfloat16* __restrict__ hhi = g_hh[s & 1];
        const __nv_bfloat16* __restrict__ hlo = g_hl[s & 1];
        __nv_bfloat16* __restrict__ ohh = g_hh[(s & 1) ^ 1];
        __nv_bfloat16* __restrict__ ohl = g_hl[(s & 1) ^ 1];

        {
            const float* gbase = g_gx + ((size_t)s * BATCH + b0) * G4 + jt0;
            #pragma unroll
            for (int t = 0; t < 2; t++) {
                int o = tid * 2 + t;
                int b = o >> 4, gate = (o >> 2) & 3, q = (o & 3) * 4;
                uint32_t d = smem_u32(gxs + b * 64 + gate * 16 + q);
                CP16(d, gbase + (size_t)b * G4 + gate * HIDDEN + q);
            }
        }
        #pragma unroll
        for (int c0 = 0; c0 < 2; c0++) {
            __nv_bfloat16* st = smem + RING0 + c0 * HSTAGE;
            uint32_t d = smem_u32(st + ld_row * PITCH + ld_c0);
            const size_t off = (size_t)(b0 + ld_row) * HIDDEN + c0 * 64 + ld_c0;
            CP16(d,                hhi + off);
            CP16(d + 2 * HTILE,    hlo + off);
            CP_COMMIT();
        }

        float accm[2][4], acc1[2][4], acc2[2][4];
        #pragma unroll
        for (int nt = 0; nt < 2; nt++)
            #pragma unroll
            for (int i = 0; i < 4; i++) {
                accm[nt][i] = 0.f; acc1[nt][i] = 0.f; acc2[nt][i] = 0.f;
            }

        for (int c = 0; c < 8; c++) {
            CP_WAIT1();
            __syncthreads();
            if (c + 2 < 8) {
                int cn = c + 2;
                __nv_bfloat16* st = smem + RING0 + (cn % 3) * HSTAGE;
                uint32_t d = smem_u32(st + ld_row * PITCH + ld_c0);
                const size_t off =
                    (size_t)(b0 + ld_row) * HIDDEN + cn * 64 + ld_c0;
                CP16(d,             hhi + off);
                CP16(d + 2 * HTILE, hlo + off);
            }
            CP_COMMIT();

            const __nv_bfloat16* Ah = smem + RING0 + (c % 3) * HSTAGE;
            const __nv_bfloat16* Al = Ah + HTILE;

            #pragma unroll
            for (int ks = 0; ks < 4; ks++) {
                uint32_t ahi[4], alo[4], bhi[4], blo[4];
                ldsm_x4(ahi, smem_u32(Ah + a_row * PITCH + ks * 16 + a_co));
                ldsm_x4(alo, smem_u32(Al + a_row * PITCH + ks * 16 + a_co));
                int krow = c * 64 + ks * 16 + b_ro;
                ldsm_x4_t(bhi, smem_u32(smem + krow * PITCH + b_co));
                ldsm_x4_t(blo, smem_u32(smem + WSPLIT + krow * PITCH + b_co));
                #pragma unroll
                for (int nt = 0; nt < 2; nt++) {
                    mma_bf16(accm[nt], ahi, bhi[nt * 2], bhi[nt * 2 + 1]);
                    mma_bf16(acc1[nt], ahi, blo[nt * 2], blo[nt * 2 + 1]);
                    mma_bf16(acc2[nt], alo, bhi[nt * 2], bhi[nt * 2 + 1]);
                }
            }
        }

        #pragma unroll
        for (int nt = 0; nt < 2; nt++)
            #pragma unroll
            for (int i = 0; i < 4; i++)
                accm[nt][i] += acc1[nt][i] + acc2[nt][i];

        // stage C into SMEM (stage-0 alias).  No barrier needed before the
        // writes: every warp passed the c=7 __syncthreads, and stage 0 was
        // last read during c=6 (before that barrier); each warp writes only
        // its own disjoint 16x16 tile.
        #pragma unroll
        for (int nt = 0; nt < 2; nt++) {
            int r0  = wb + (lane >> 2);
            int col = wn + nt * 8 + (lane & 3) * 2;
            *(float2*)&Csm[r0 * 68 + col] =
                make_float2(accm[nt][0], accm[nt][1]);
            *(float2*)&Csm[(r0 + 8) * 68 + col] =
                make_float2(accm[nt][2], accm[nt][3]);
        }
        __syncthreads();

        #pragma unroll
        for (int t = 0; t < 2; t++) {
            int idx = tid + t * 512;
            int jl = idx & 15, bl = idx >> 4;
            int b = b0 + bl, j = jt0 + jl;
            float4 gq = *(const float4*)&Csm[bl * 68 + jl * 4];  // i,f,g,o
            const float* gr = gxs + bl * 64;
            float gi = gq.x + gr[jl]      + bh[t][0];
            float gf = gq.y + gr[16 + jl] + bh[t][1];
            float gg = gq.z + gr[32 + jl] + bh[t][2];
            float go = gq.w + gr[48 + jl] + bh[t][3];
            float ig = sigf(gi), fg = sigf(gf);
            float gv = tanhf(gg), og = sigf(go);
            float cn = fg * creg[t] + ig * gv;
            creg[t] = cn;
            float hn = og * tanhf(cn);
            int ci = b * HIDDEN + j;
            __nv_bfloat16 hi = __float2bfloat16(hn);
            ohh[ci] = hi;
            ohl[ci] = __float2bfloat16(hn - __bfloat162float(hi));
        }

        // ---- sub-group epoch barrier (32 CTAs sharing this b-tile) ----
        __syncthreads();
        if (tid == 0) {
            FENCE_ACQREL_GPU();                    // release h stores
            unsigned a = atomicAdd(cntp, 1u);
            if (a == 31u) {
                *cntp = 0u;
                FENCE_ACQREL_GPU();                // order reset + acquire
                *(volatile unsigned*)epochp = (unsigned)(s + 1);
            } else {
                while (*(volatile unsigned*)epochp < (unsigned)(s + 1)) { }
                FENCE_ACQREL_GPU();                // acquire h stores
            }
        }
        __syncthreads();
    }
}

// ---------------------------------------------------------------------------
// Init
// ---------------------------------------------------------------------------
__global__ void k_init() {
    int i = blockIdx.x * blockDim.x + threadIdx.x;
    if (i < BATCH * HIDDEN) {
        g_hh[0][i] = __float2bfloat16(0.f);
        g_hl[0][i] = __float2bfloat16(0.f);
    }
    if (i < 4 * 32) { g_cnt4[i] = 0u; g_epoch4[i] = 0u; }
}

// ---------------------------------------------------------------------------
// Kernel C: logits = h_T @ W_fc^T + b_fc
// ---------------------------------------------------------------------------
__global__ __launch_bounds__(128) void k_fc(
    const float* __restrict__ W_fc, const float* __restrict__ b_fc,
    float* __restrict__ out)
{
    const int b   = blockIdx.x;
    const int tid = threadIdx.x;

    float p[NOUT];
    #pragma unroll
    for (int o = 0; o < NOUT; o++) p[o] = 0.f;

    for (int jj = tid; jj < HIDDEN; jj += 128) {
        float hv = __bfloat162float(g_hh[0][b * HIDDEN + jj]) +
                   __bfloat162float(g_hl[0][b * HIDDEN + jj]);
        #pragma unroll
        for (int o = 0; o < NOUT; o++) p[o] += hv * W_fc[o * HIDDEN + jj];
    }

    __shared__ float redm[NOUT][128];
    #pragma unroll
    for (int o = 0; o < NOUT; o++) redm[o][tid] = p[o];
    __syncthreads();
    for (int st = 64; st > 0; st >>= 1) {
        if (tid < st) {
            #pragma unroll
            for (int o = 0; o < NOUT; o++) redm[o][tid] += redm[o][tid + st];
        }
        __syncthreads();
    }
    if (tid < NOUT) out[b * NOUT + tid] = redm[tid][0] + b_fc[tid];
}

// ---------------------------------------------------------------------------
// Launch
// ---------------------------------------------------------------------------
extern "C" void kernel_launch(void* const* d_in, const int* in_sizes, int n_in,
                              void* d_out, int out_size)
{
    const int*   tokens = (const int*)  d_in[0];
    const float* emb    = (const float*)d_in[1];
    const float* W_ih   = (const float*)d_in[2];
    const float* b_ih   = (const float*)d_in[3];
    const float* W_hh   = (const float*)d_in[4];
    const float* b_hh   = (const float*)d_in[5];
    const float* W_fc   = (const float*)d_in[6];
    const float* b_fc   = (const float*)d_in[7];
    float* out = (float*)d_out;

    static bool attr_set = false;
    if (!attr_set) {
        cudaFuncSetAttribute(k_lstm_persist,
                             cudaFuncAttributeMaxDynamicSharedMemorySize,
                             SMEM_PERSIST);
        cudaFuncSetAttribute(k_embed_mma,
                             cudaFuncAttributeMaxDynamicSharedMemorySize,
                             SMEM_EMB);
        attr_set = true;
    }

    k_init<<<(BATCH * HIDDEN + 255) / 256, 256>>>();
    k_prep_w<<<(HIDDEN * G4) / 256, 256>>>(W_hh);
    k_prep_wih<<<(KA * G4) / 256, 256>>>(W_ih);
    k_prep_emb<<<((size_t)VOCAB * KA) / 256, 256>>>(emb);

    dim3 gE(G4 / 64, (BATCH * SEQ) / 128);   // (32, 1024)
    k_embed_mma<<<gE, 512, SMEM_EMB>>>(tokens, b_ih);

    k_lstm_persist<<<128, 512, SMEM_PERSIST>>>(b_hh);

    k_fc<<<BATCH, 128>>>(W_fc, b_fc, out);
}